// round 13
// baseline (speedup 1.0000x reference)
#include <cuda_runtime.h>
#include <cuda_bf16.h>
#include <cuda_fp16.h>
#include <cstdint>

#define B_    16
#define N_    16
#define D_    4096
#define H_    32
#define HK_   8
#define REP_  4
#define DH_   128
#define PCOLS 6144
#define SCALE 0.08838834764831844f
#define WB_ROWS 10240
#define TPC   2112
#define NSP2  8              /* 4 kv-splits x 2 warp t-halves */

typedef unsigned long long u64;

__device__ __forceinline__ void cpa16(uint32_t dst, const void* src, int sz) {
    asm volatile("cp.async.cg.shared.global [%0], [%1], 16, %2;"
                 :: "r"(dst), "l"(src), "r"(sz));
}
__device__ __forceinline__ void cpa_commit() {
    asm volatile("cp.async.commit_group;" ::: "memory");
}
__device__ __forceinline__ void cpa_wait0() {
    asm volatile("cp.async.wait_group 0;" ::: "memory");
}
__device__ __forceinline__ void cpa_wait1() {
    asm volatile("cp.async.wait_group 1;" ::: "memory");
}
__device__ __forceinline__ void ldsm4(uint32_t* r, uint32_t addr) {
    asm volatile("ldmatrix.sync.aligned.m8n8.x4.shared.b16 {%0,%1,%2,%3}, [%4];"
                 : "=r"(r[0]), "=r"(r[1]), "=r"(r[2]), "=r"(r[3]) : "r"(addr));
}
__device__ __forceinline__ void mma16816(float* c, const uint32_t* a, const uint32_t* b) {
    asm volatile("mma.sync.aligned.m16n8k16.row.col.f32.bf16.bf16.f32 "
        "{%0,%1,%2,%3}, {%4,%5,%6,%7}, {%8,%9}, {%0,%1,%2,%3};"
        : "+f"(c[0]), "+f"(c[1]), "+f"(c[2]), "+f"(c[3])
        : "r"(a[0]), "r"(a[1]), "r"(a[2]), "r"(a[3]), "r"(b[0]), "r"(b[1]));
}
__device__ __forceinline__ void mma16816h(float* c, const uint32_t* a, const uint32_t* b) {
    asm volatile("mma.sync.aligned.m16n8k16.row.col.f32.f16.f16.f32 "
        "{%0,%1,%2,%3}, {%4,%5,%6,%7}, {%8,%9}, {%0,%1,%2,%3};"
        : "+f"(c[0]), "+f"(c[1]), "+f"(c[2]), "+f"(c[3])
        : "r"(a[0]), "r"(a[1]), "r"(a[2]), "r"(a[3]), "r"(b[0]), "r"(b[1]));
}
__device__ __forceinline__ uint32_t cvt2(float hi, float lo) {
    uint32_t r; asm("cvt.rn.bf16x2.f32 %0, %1, %2;" : "=r"(r) : "f"(hi), "f"(lo));
    return r;
}
__device__ __forceinline__ uint32_t cvth2(float hi, float lo) {
    uint32_t r; asm("cvt.rn.f16x2.f32 %0, %1, %2;" : "=r"(r) : "f"(hi), "f"(lo));
    return r;
}
__device__ __forceinline__ void split2(float a, float b, uint32_t& h, uint32_t& lo) {
    h = cvt2(b, a);
    float ha = __uint_as_float(h << 16);
    float hb = __uint_as_float(h & 0xffff0000u);
    lo = cvt2(b - hb, a - ha);
}

// ---------------- scratch ----------------
__device__ float g_pbuf[256 * PCOLS];
__device__ float g_q[B_ * H_ * N_ * DH_];
__device__ float g_k[B_ * HK_ * N_ * DH_];
__device__ float g_v[B_ * HK_ * N_ * DH_];
__device__ float g_pacc[128 * NSP2 * 64 * 128];
__device__ float g_pl[128 * NSP2 * 64];
__device__ __align__(16) __nv_bfloat16 g_wh[WB_ROWS * 4096];
__device__ __align__(16) __nv_bfloat16 g_wl[WB_ROWS * 4096];
__device__ __align__(16) __nv_bfloat16 g_xh[256 * 4096];
__device__ __align__(16) __nv_bfloat16 g_xl[256 * 4096];
__device__ __align__(16) __nv_bfloat16 g_zh[256 * 4096];
__device__ __align__(16) __nv_bfloat16 g_zl[256 * 4096];
__device__ __align__(16) __half       g_kf[128 * TPC * 128];
__device__ __align__(16) __half       g_vt[128 * 128 * TPC];

// ---------------- weight transpose + bf16 split ----------------
__global__ __launch_bounds__(256) void conv_w(
    const float* __restrict__ wq, const float* __restrict__ wk,
    const float* __restrict__ wv, const float* __restrict__ wo)
{
    __shared__ float t[32][33];
    const int k0 = blockIdx.x << 5, n0 = blockIdx.y << 5;
    const int tx = threadIdx.x & 31, ty = threadIdx.x >> 5;
    const float* src; int nn, pitch;
    if (n0 < 4096)      { src = wq; nn = n0;        pitch = 4096; }
    else if (n0 < 5120) { src = wk; nn = n0 - 4096; pitch = 1024; }
    else if (n0 < 6144) { src = wv; nn = n0 - 5120; pitch = 1024; }
    else                { src = wo; nn = n0 - 6144; pitch = 4096; }
#pragma unroll
    for (int i = 0; i < 4; i++)
        t[ty + (i << 3)][tx] = src[(long long)(k0 + ty + (i << 3)) * pitch + nn + tx];
    __syncthreads();
#pragma unroll
    for (int i = 0; i < 4; i++) {
        float v = t[tx][ty + (i << 3)];
        __nv_bfloat16 h = __float2bfloat16(v);
        long long o = (long long)(n0 + ty + (i << 3)) * 4096 + k0 + tx;
        g_wh[o] = h;
        g_wl[o] = __float2bfloat16(v - __bfloat162float(h));
    }
}

__global__ __launch_bounds__(256) void conv_split(
    const float* __restrict__ src, __nv_bfloat16* __restrict__ hh,
    __nv_bfloat16* __restrict__ ll, int n)
{
    int i = blockIdx.x * blockDim.x + threadIdx.x;
    if (i >= n) return;
    float v = src[i];
    __nv_bfloat16 h = __float2bfloat16(v);
    hh[i] = h;
    ll[i] = __float2bfloat16(v - __bfloat162float(h));
}

// ---------------- HMMA bf16x3 GEMM: 128x128 tiles, 2 CTAs/SM ----------------
#define HSM_STAGE 32768
#define HSM_B_OFF 16384
#define HSM_TOT   65536

__global__ __launch_bounds__(256, 2) void hgemm(
    const __nv_bfloat16* __restrict__ Ah, const __nv_bfloat16* __restrict__ Al,
    int wb_off, float* __restrict__ C, int ldc)
{
    extern __shared__ char smr[];
    const int tid = threadIdx.x;
    const int l = tid & 31, w = tid >> 5;
    const int wm = w >> 2, wn = w & 3;
    const int bn = blockIdx.x << 7, bm = blockIdx.y << 7;
    const uint32_t smb = (uint32_t)__cvta_generic_to_shared(smr);

    const __nv_bfloat16* ah = Ah + (long long)bm * 4096;
    const __nv_bfloat16* al = Al + (long long)bm * 4096;
    const __nv_bfloat16* bh = g_wh + (long long)(wb_off + bn) * 4096;
    const __nv_bfloat16* bl = g_wl + (long long)(wb_off + bn) * 4096;

    float acc[4][4][4];
#pragma unroll
    for (int i = 0; i < 4; i++)
#pragma unroll
        for (int j = 0; j < 4; j++)
#pragma unroll
            for (int q = 0; q < 4; q++) acc[i][j][q] = 0.f;

    auto load_stage = [&](uint32_t sbase, int k0) {
#pragma unroll
        for (int i = 0; i < 8; i++) {
            int s = tid + (i << 8);
            int idx = s & 1023;
            int row = idx >> 3, g = idx & 7;
            const __nv_bfloat16 *hsrc, *lsrc;
            uint32_t dst;
            if (s < 1024) { hsrc = ah; lsrc = al; dst = sbase; }
            else          { hsrc = bh; lsrc = bl; dst = sbase + HSM_B_OFF; }
            const __nv_bfloat16* src = (g < 4 ? hsrc : lsrc)
                                     + (long long)row * 4096 + k0 + ((g & 3) << 3);
            cpa16(dst + row * 128 + ((g ^ (row & 7)) << 4), src, 16);
        }
        cpa_commit();
    };

    load_stage(smb, 0);

    const int a_row = (l & 15);
    const int a_half = l >> 4;
    const int b_rl = (l & 7) + ((l >> 4) << 3);
    const int b_half = (l >> 3) & 1;

    for (int c = 0; c < 128; c++) {
        cpa_wait0();
        __syncthreads();
        const uint32_t st = smb + (c & 1) * HSM_STAGE;
        if (c + 1 < 128) load_stage(smb + ((c + 1) & 1) * HSM_STAGE, (c + 1) << 5);

#pragma unroll
        for (int ks = 0; ks < 2; ks++) {
            uint32_t ahf[4][4], alf[4][4], bhf[2][4], blf[2][4];
#pragma unroll
            for (int mt = 0; mt < 4; mt++) {
                int row = (wm << 6) + (mt << 4) + a_row;
                int gh = (ks << 1) + a_half;
                uint32_t base = st + row * 128;
                ldsm4(ahf[mt], base + ((gh ^ (row & 7)) << 4));
                int gl = gh + 4;
                ldsm4(alf[mt], base + ((gl ^ (row & 7)) << 4));
            }
#pragma unroll
            for (int np = 0; np < 2; np++) {
                int row = (wn << 5) + (np << 4) + b_rl;
                int gh = (ks << 1) + b_half;
                uint32_t base = st + HSM_B_OFF + row * 128;
                ldsm4(bhf[np], base + ((gh ^ (row & 7)) << 4));
                int gl = gh + 4;
                ldsm4(blf[np], base + ((gl ^ (row & 7)) << 4));
            }
#pragma unroll
            for (int mt = 0; mt < 4; mt++)
#pragma unroll
                for (int np = 0; np < 2; np++)
#pragma unroll
                    for (int hh = 0; hh < 2; hh++) {
                        float* at = acc[mt][(np << 1) + hh];
                        mma16816(at, ahf[mt], &bhf[np][hh << 1]);
                        mma16816(at, ahf[mt], &blf[np][hh << 1]);
                        mma16816(at, alf[mt], &bhf[np][hh << 1]);
                    }
        }
        __syncthreads();
    }

#pragma unroll
    for (int mt = 0; mt < 4; mt++) {
#pragma unroll
        for (int nt = 0; nt < 4; nt++) {
            long long r0 = bm + (wm << 6) + (mt << 4) + (l >> 2);
            int col = bn + (wn << 5) + (nt << 3) + ((l & 3) << 1);
            float* cp = C + r0 * ldc + col;
            *(float2*)cp             = make_float2(acc[mt][nt][0], acc[mt][nt][1]);
            *(float2*)(cp + 8 * ldc) = make_float2(acc[mt][nt][2], acc[mt][nt][3]);
        }
    }
}

// ---------------- RoPE + rearrange ----------------
__global__ __launch_bounds__(256) void rope_qk(
    const float* __restrict__ pbuf, const float* __restrict__ fc, const float* __restrict__ fs)
{
    int i = blockIdx.x * blockDim.x + threadIdx.x;
    const int TOT = B_ * N_ * (H_ + HK_) * 64;
    if (i >= TOT) return;
    int pr   = i & 63;
    int head = (i >> 6) % (H_ + HK_);
    int bn   = (i >> 6) / (H_ + HK_);
    int n    = bn % N_;
    int b    = bn / N_;
    float c = fc[n * 64 + pr];
    float s = fs[n * 64 + pr];
    const float* row = pbuf + (long long)(b * N_ + n) * PCOLS;
    if (head < H_) {
        float a  = row[head * DH_ + 2 * pr];
        float bb = row[head * DH_ + 2 * pr + 1];
        float* q = g_q + ((long long)(b * H_ + head) * N_ + n) * DH_ + 2 * pr;
        q[0] = (a * c - bb * s) * SCALE;
        q[1] = (a * s + bb * c) * SCALE;
    } else {
        int hk = head - H_;
        float a  = row[H_ * DH_ + hk * DH_ + 2 * pr];
        float bb = row[H_ * DH_ + hk * DH_ + 2 * pr + 1];
        float* k = g_k + ((long long)(b * HK_ + hk) * N_ + n) * DH_ + 2 * pr;
        k[0] = a * c - bb * s;
        k[1] = a * s + bb * c;
    }
}

__global__ __launch_bounds__(256) void copy_v(const float* __restrict__ pbuf)
{
    int i = blockIdx.x * blockDim.x + threadIdx.x;
    if (i >= B_ * HK_ * N_ * DH_) return;
    int d  = i & 127;
    int n  = (i >> 7) & 15;
    int hk = (i >> 11) & 7;
    int b  = i >> 14;
    g_v[i] = pbuf[(long long)(b * N_ + n) * PCOLS + (H_ + HK_) * DH_ + hk * DH_ + d];
}

// ---------------- K cache -> fp16 [bhk][t][d] ----------------
__global__ __launch_bounds__(256) void conv_k(
    const float* __restrict__ cache_k, const int* __restrict__ sp, int ctx, int Tpad)
{
    int i = blockIdx.x * blockDim.x + threadIdx.x;
    int d4  = i & 31;
    int t   = (i >> 5) % Tpad;
    int bhk = i / (Tpad << 5);
    if (bhk >= 128) return;
    const int start = sp[0], tend = start + N_;
    float4 v;
    if (t < start)
        v = *(const float4*)(cache_k + ((long long)bhk * ctx + t) * DH_ + (d4 << 2));
    else if (t < tend)
        v = *(const float4*)(g_k + ((long long)bhk * N_ + (t - start)) * DH_ + (d4 << 2));
    else
        v = make_float4(0.f, 0.f, 0.f, 0.f);
    long long o = ((long long)bhk * Tpad + t) * 128 + (d4 << 2);
    *(uint2*)(g_kf + o) = make_uint2(cvth2(v.y, v.x), cvth2(v.w, v.z));
}

// ---------------- V cache -> fp16 transposed [bhk][d][t] ----------------
__global__ __launch_bounds__(256) void conv_vt(
    const float* __restrict__ cache_v, const int* __restrict__ sp, int ctx, int Tpad)
{
    __shared__ float ts[32][33];
    const int bhk = blockIdx.x, tb = blockIdx.y << 5, db = blockIdx.z << 5;
    const int tx = threadIdx.x & 31, ty = threadIdx.x >> 5;
    const int start = sp[0], tend = start + N_;
#pragma unroll
    for (int i = 0; i < 4; i++) {
        int t = tb + ty + (i << 3);
        float v;
        if (t < start)
            v = cache_v[((long long)bhk * ctx + t) * DH_ + db + tx];
        else if (t < tend)
            v = g_v[((long long)bhk * N_ + (t - start)) * DH_ + db + tx];
        else
            v = 0.f;
        ts[ty + (i << 3)][tx] = v;
    }
    __syncthreads();
#pragma unroll
    for (int i = 0; i < 4; i++) {
        int d = db + ty + (i << 3);
        g_vt[((long long)bhk * 128 + d) * Tpad + tb + tx] =
            __float2half(ts[tx][ty + (i << 3)]);
    }
}

// ---------------- attn: fp16 QK + fp16 PV; 3-stage pipeline; 4 kv-splits ----------------
#define ASM_Q   0
#define ASM_ST  16384
#define ASM_STRIDE 32768
#define ASM_TOT (16384 + 3 * 32768)

__global__ __launch_bounds__(256, 1) void attn(const int* __restrict__ sp, int Tpad)
{
    extern __shared__ char smr[];
    const int tid = threadIdx.x;
    const int l = tid & 31, w = tid >> 5;
    const int wm = w >> 1, wn = w & 1;
    const int bhk = blockIdx.x;
    const int ks  = blockIdx.y;          // 0..3
    const int start = sp[0];
    const int tend  = start + N_;
    const uint32_t smb = (uint32_t)__cvta_generic_to_shared(smr);

    const float* qbase = g_q + ((long long)(bhk >> 3) * H_ + (bhk & 7) * REP_) * N_ * DH_;
#pragma unroll
    for (int i = 0; i < 4; i++) {
        int j = tid + (i << 8);
        int row = j >> 4, g = j & 15;
        const float* src = qbase + row * 128 + (g << 3);
        float4 f0 = *(const float4*)src;
        float4 f1 = *(const float4*)(src + 4);
        uint32_t off = row * 256 + ((g ^ (row & 7)) << 4);
        *(uint4*)(smr + ASM_Q + off) = make_uint4(
            cvth2(f0.y, f0.x), cvth2(f0.w, f0.z), cvth2(f1.y, f1.x), cvth2(f1.w, f1.z));
    }

    auto load_stage = [&](uint32_t sbase, int t0) {
#pragma unroll
        for (int i = 0; i < 8; i++) {
            int s = tid + (i << 8);
            if (s < 1024) {
                int row = s >> 4, g = s & 15;
                const __half* src = g_kf
                    + ((long long)bhk * Tpad + t0 + row) * 128 + (g << 3);
                cpa16(sbase + row * 256 + ((g ^ (row & 7)) << 4), src, 16);
            } else {
                int idx = s - 1024;
                int row = idx >> 3, g = idx & 7;
                const __half* src = g_vt
                    + ((long long)bhk * 128 + row) * Tpad + t0 + (g << 3);
                cpa16(sbase + 16384 + row * 128 + ((g ^ (row & 7)) << 4), src, 16);
            }
        }
        cpa_commit();
    };

    const int nc = (tend - ks * 64 + 255) >> 8;    // stride 256 across 4 splits
    load_stage(smb + ASM_ST, ks * 64);
    if (nc > 1) load_stage(smb + ASM_ST + ASM_STRIDE, ks * 64 + 256);

    float oacc[16][4];
#pragma unroll
    for (int i = 0; i < 16; i++)
#pragma unroll
        for (int q = 0; q < 4; q++) oacc[i][q] = 0.f;
    float lsumA = 0.f, lsumB = 0.f;
    const int limA = start + (l >> 2);
    const int limB = limA + 8;

    const int a_row = l & 15, a_half = l >> 4;
    const int b_rl = (l & 7) + ((l >> 4) << 3);
    const int b_half = (l >> 3) & 1;
    const int tg = l & 3;

    for (int ci = 0; ci < nc; ci++) {
        const int t0 = ks * 64 + (ci << 8);
        if (ci + 2 <= nc) cpa_wait1(); else cpa_wait0();
        __syncthreads();
        const uint32_t st = smb + ASM_ST + (ci % 3) * ASM_STRIDE;
        if (ci + 2 < nc)
            load_stage(smb + ASM_ST + ((ci + 2) % 3) * ASM_STRIDE, t0 + 512);

        float sacc[4][4];
#pragma unroll
        for (int i = 0; i < 4; i++)
#pragma unroll
            for (int q = 0; q < 4; q++) sacc[i][q] = 0.f;
#pragma unroll
        for (int kk = 0; kk < 8; kk++) {
            uint32_t ah[4], bh[2][4];
            {
                int row = (wm << 4) + a_row;
                int g = (kk << 1) + a_half;
                ldsm4(ah, smb + ASM_Q + row * 256 + ((g ^ (row & 7)) << 4));
            }
#pragma unroll
            for (int np = 0; np < 2; np++) {
                int row = (wn << 5) + (np << 4) + b_rl;
                int g = (kk << 1) + b_half;
                ldsm4(bh[np], st + row * 256 + ((g ^ (row & 7)) << 4));
            }
#pragma unroll
            for (int np = 0; np < 2; np++)
#pragma unroll
                for (int hh = 0; hh < 2; hh++)
                    mma16816h(sacc[(np << 1) + hh], ah, &bh[np][hh << 1]);
        }

        uint32_t pa[2][4];
#pragma unroll
        for (int nt = 0; nt < 4; nt++) {
            int tb = t0 + (wn << 5) + (nt << 3) + (tg << 1);
            float p0 = (tb     <= limA) ? __expf(sacc[nt][0]) : 0.f;
            float p1 = (tb + 1 <= limA) ? __expf(sacc[nt][1]) : 0.f;
            float p2 = (tb     <= limB) ? __expf(sacc[nt][2]) : 0.f;
            float p3 = (tb + 1 <= limB) ? __expf(sacc[nt][3]) : 0.f;
            lsumA += p0 + p1;
            lsumB += p2 + p3;
            int kt = nt >> 1, hf = nt & 1;
            pa[kt][(hf << 1) + 0] = cvth2(p1, p0);
            pa[kt][(hf << 1) + 1] = cvth2(p3, p2);
        }

#pragma unroll
        for (int kt = 0; kt < 2; kt++) {
#pragma unroll
            for (int np = 0; np < 8; np++) {
                int row = (np << 4) + b_rl;
                int g = (wn << 2) + (kt << 1) + b_half;
                uint32_t bv[4];
                ldsm4(bv, st + 16384 + row * 128 + ((g ^ (row & 7)) << 4));
                mma16816h(oacc[(np << 1) + 0], pa[kt], &bv[0]);
                mma16816h(oacc[(np << 1) + 1], pa[kt], &bv[2]);
            }
        }
    }

#pragma unroll
    for (int m = 1; m < 4; m <<= 1) {
        lsumA += __shfl_xor_sync(0xffffffffu, lsumA, m);
        lsumB += __shfl_xor_sync(0xffffffffu, lsumB, m);
    }

    const int spn = (ks << 1) + wn;
    const long long pb = ((long long)bhk * NSP2 + spn) * 64;
    if (tg == 0) {
        g_pl[pb + (wm << 4) + (l >> 2)]     = lsumA;
        g_pl[pb + (wm << 4) + (l >> 2) + 8] = lsumB;
    }
#pragma unroll
    for (int nt = 0; nt < 16; nt++) {
        long long r0 = pb + (wm << 4) + (l >> 2);
        int d = (nt << 3) + (tg << 1);
        *(float2*)(g_pacc + r0 * 128 + d)       = make_float2(oacc[nt][0], oacc[nt][1]);
        *(float2*)(g_pacc + (r0 + 8) * 128 + d) = make_float2(oacc[nt][2], oacc[nt][3]);
    }
}

// ---------------- combine partials -> z (bf16 hi/lo directly) ----------------
__global__ __launch_bounds__(256) void attn_combine(
    __nv_bfloat16* __restrict__ zh, __nv_bfloat16* __restrict__ zl)
{
    int idx = blockIdx.x * blockDim.x + threadIdx.x;
    if (idx >= 128 * 64 * 128) return;
    int d    = idx & 127;
    int row  = (idx >> 7) & 63;
    int bhk  = idx >> 13;
    float a = 0.f, lv = 0.f;
#pragma unroll
    for (int spn = 0; spn < NSP2; spn++) {
        long long base = ((long long)bhk * NSP2 + spn) * 64 + row;
        a  += g_pacc[base * 128 + d];
        lv += g_pl[base];
    }
    int r = row >> 4, n = row & 15;
    int b = bhk >> 3, hk = bhk & 7;
    float v = a / lv;
    __nv_bfloat16 h = __float2bfloat16(v);
    long long o = (long long)(b * N_ + n) * D_ + (hk * REP_ + r) * DH_ + d;
    zh[o] = h;
    zl[o] = __float2bfloat16(v - __bfloat162float(h));
}

// ---------------- launch ----------------
extern "C" void kernel_launch(void* const* d_in, const int* in_sizes, int n_in,
                              void* d_out, int out_size)
{
    const float* x  = (const float*)d_in[0];
    const float* fc = (const float*)d_in[1];
    const float* fs = (const float*)d_in[2];
    const float* ck = (const float*)d_in[4];
    const float* cv = (const float*)d_in[5];
    const float* wq = (const float*)d_in[6];
    const float* wk = (const float*)d_in[7];
    const float* wv = (const float*)d_in[8];
    const float* wo = (const float*)d_in[9];
    const int*   sp = (const int*)d_in[10];
    float* out = (float*)d_out;

    int ctx  = in_sizes[4] / (B_ * HK_ * DH_);
    int T    = in_sizes[3] / N_;
    int Tpad = ((T + 63) / 64) * 64;
    if (Tpad > TPC) Tpad = TPC;

    float* pbuf; cudaGetSymbolAddress((void**)&pbuf, g_pbuf);
    __nv_bfloat16 *xh, *xl, *zh, *zl;
    cudaGetSymbolAddress((void**)&xh, g_xh);
    cudaGetSymbolAddress((void**)&xl, g_xl);
    cudaGetSymbolAddress((void**)&zh, g_zh);
    cudaGetSymbolAddress((void**)&zl, g_zl);

    dim3 blk(256);

    conv_w<<<dim3(128, 320), blk>>>(wq, wk, wv, wo);
    conv_split<<<(256 * 4096 + 255) / 256, blk>>>(x, xh, xl, 256 * 4096);

    cudaFuncSetAttribute(hgemm, cudaFuncAttributeMaxDynamicSharedMemorySize, HSM_TOT);
    hgemm<<<dim3(48, 2), blk, HSM_TOT>>>(xh, xl, 0, pbuf, PCOLS);

    rope_qk<<<(B_ * N_ * (H_ + HK_) * 64 + 255) / 256, blk>>>(pbuf, fc, fs);
    copy_v<<<(B_ * HK_ * N_ * DH_ + 255) / 256, blk>>>(pbuf);

    conv_k<<<(128 * Tpad * 32 + 255) / 256, blk>>>(ck, sp, ctx, Tpad);
    conv_vt<<<dim3(128, Tpad / 32, 4), blk>>>(cv, sp, ctx, Tpad);

    cudaFuncSetAttribute(attn, cudaFuncAttributeMaxDynamicSharedMemorySize, ASM_TOT);
    attn<<<dim3(128, 4), blk, ASM_TOT>>>(sp, Tpad);
    attn_combine<<<(128 * 64 * 128 + 255) / 256, blk>>>(zh, zl);

    hgemm<<<dim3(32, 2), blk, HSM_TOT>>>(zh, zl, 6144, out, D_);
}

// round 14
// speedup vs baseline: 1.0796x; 1.0796x over previous
#include <cuda_runtime.h>
#include <cuda_bf16.h>
#include <cuda_fp16.h>
#include <cstdint>

#define B_    16
#define N_    16
#define D_    4096
#define H_    32
#define HK_   8
#define REP_  4
#define DH_   128
#define PCOLS 6144
#define SCALE 0.08838834764831844f
#define WB_ROWS 10240
#define TPC   2112
#define NSP2  16             /* 8 kv-splits x 2 warp t-halves */

typedef unsigned long long u64;

__device__ __forceinline__ void cpa16(uint32_t dst, const void* src, int sz) {
    asm volatile("cp.async.cg.shared.global [%0], [%1], 16, %2;"
                 :: "r"(dst), "l"(src), "r"(sz));
}
__device__ __forceinline__ void cpa_commit() {
    asm volatile("cp.async.commit_group;" ::: "memory");
}
__device__ __forceinline__ void cpa_wait0() {
    asm volatile("cp.async.wait_group 0;" ::: "memory");
}
__device__ __forceinline__ void cpa_wait1() {
    asm volatile("cp.async.wait_group 1;" ::: "memory");
}
__device__ __forceinline__ void ldsm4(uint32_t* r, uint32_t addr) {
    asm volatile("ldmatrix.sync.aligned.m8n8.x4.shared.b16 {%0,%1,%2,%3}, [%4];"
                 : "=r"(r[0]), "=r"(r[1]), "=r"(r[2]), "=r"(r[3]) : "r"(addr));
}
__device__ __forceinline__ void mma16816(float* c, const uint32_t* a, const uint32_t* b) {
    asm volatile("mma.sync.aligned.m16n8k16.row.col.f32.bf16.bf16.f32 "
        "{%0,%1,%2,%3}, {%4,%5,%6,%7}, {%8,%9}, {%0,%1,%2,%3};"
        : "+f"(c[0]), "+f"(c[1]), "+f"(c[2]), "+f"(c[3])
        : "r"(a[0]), "r"(a[1]), "r"(a[2]), "r"(a[3]), "r"(b[0]), "r"(b[1]));
}
__device__ __forceinline__ void mma16816h(float* c, const uint32_t* a, const uint32_t* b) {
    asm volatile("mma.sync.aligned.m16n8k16.row.col.f32.f16.f16.f32 "
        "{%0,%1,%2,%3}, {%4,%5,%6,%7}, {%8,%9}, {%0,%1,%2,%3};"
        : "+f"(c[0]), "+f"(c[1]), "+f"(c[2]), "+f"(c[3])
        : "r"(a[0]), "r"(a[1]), "r"(a[2]), "r"(a[3]), "r"(b[0]), "r"(b[1]));
}
__device__ __forceinline__ uint32_t cvt2(float hi, float lo) {
    uint32_t r; asm("cvt.rn.bf16x2.f32 %0, %1, %2;" : "=r"(r) : "f"(hi), "f"(lo));
    return r;
}
__device__ __forceinline__ uint32_t cvth2(float hi, float lo) {
    uint32_t r; asm("cvt.rn.f16x2.f32 %0, %1, %2;" : "=r"(r) : "f"(hi), "f"(lo));
    return r;
}
__device__ __forceinline__ void split2(float a, float b, uint32_t& h, uint32_t& lo) {
    h = cvt2(b, a);
    float ha = __uint_as_float(h << 16);
    float hb = __uint_as_float(h & 0xffff0000u);
    lo = cvt2(b - hb, a - ha);
}

// ---------------- scratch ----------------
__device__ float g_pbuf[256 * PCOLS];
__device__ float g_q[B_ * H_ * N_ * DH_];
__device__ float g_k[B_ * HK_ * N_ * DH_];
__device__ float g_v[B_ * HK_ * N_ * DH_];
__device__ float g_pacc[128 * NSP2 * 64 * 128];
__device__ float g_pl[128 * NSP2 * 64];
__device__ __align__(16) __nv_bfloat16 g_wh[WB_ROWS * 4096];
__device__ __align__(16) __nv_bfloat16 g_wl[WB_ROWS * 4096];
__device__ __align__(16) __nv_bfloat16 g_xh[256 * 4096];
__device__ __align__(16) __nv_bfloat16 g_xl[256 * 4096];
__device__ __align__(16) __nv_bfloat16 g_zh[256 * 4096];
__device__ __align__(16) __nv_bfloat16 g_zl[256 * 4096];
__device__ __align__(16) __half       g_kf[128 * TPC * 128];
__device__ __align__(16) __half       g_vt[128 * 128 * TPC];

// ---------------- weight transpose + bf16 split ----------------
__global__ __launch_bounds__(256) void conv_w(
    const float* __restrict__ wq, const float* __restrict__ wk,
    const float* __restrict__ wv, const float* __restrict__ wo)
{
    __shared__ float t[32][33];
    const int k0 = blockIdx.x << 5, n0 = blockIdx.y << 5;
    const int tx = threadIdx.x & 31, ty = threadIdx.x >> 5;
    const float* src; int nn, pitch;
    if (n0 < 4096)      { src = wq; nn = n0;        pitch = 4096; }
    else if (n0 < 5120) { src = wk; nn = n0 - 4096; pitch = 1024; }
    else if (n0 < 6144) { src = wv; nn = n0 - 5120; pitch = 1024; }
    else                { src = wo; nn = n0 - 6144; pitch = 4096; }
#pragma unroll
    for (int i = 0; i < 4; i++)
        t[ty + (i << 3)][tx] = src[(long long)(k0 + ty + (i << 3)) * pitch + nn + tx];
    __syncthreads();
#pragma unroll
    for (int i = 0; i < 4; i++) {
        float v = t[tx][ty + (i << 3)];
        __nv_bfloat16 h = __float2bfloat16(v);
        long long o = (long long)(n0 + ty + (i << 3)) * 4096 + k0 + tx;
        g_wh[o] = h;
        g_wl[o] = __float2bfloat16(v - __bfloat162float(h));
    }
}

__global__ __launch_bounds__(256) void conv_split(
    const float* __restrict__ src, __nv_bfloat16* __restrict__ hh,
    __nv_bfloat16* __restrict__ ll, int n)
{
    int i = blockIdx.x * blockDim.x + threadIdx.x;
    if (i >= n) return;
    float v = src[i];
    __nv_bfloat16 h = __float2bfloat16(v);
    hh[i] = h;
    ll[i] = __float2bfloat16(v - __bfloat162float(h));
}

// ---------------- HMMA bf16x3 GEMM: 128x64 tiles (R12 config) ----------------
#define HSM_STAGE 24576
#define HSM_B_OFF 16384
#define HSM_TOT   49152

__global__ __launch_bounds__(256) void hgemm(
    const __nv_bfloat16* __restrict__ Ah, const __nv_bfloat16* __restrict__ Al,
    int wb_off, float* __restrict__ C, int ldc)
{
    extern __shared__ char smr[];
    const int tid = threadIdx.x;
    const int l = tid & 31, w = tid >> 5;
    const int wm = w >> 1, wn = w & 1;
    const int bn = blockIdx.x << 6, bm = blockIdx.y << 7;
    const uint32_t smb = (uint32_t)__cvta_generic_to_shared(smr);

    const __nv_bfloat16* ah = Ah + (long long)bm * 4096;
    const __nv_bfloat16* al = Al + (long long)bm * 4096;
    const __nv_bfloat16* bh = g_wh + (long long)(wb_off + bn) * 4096;
    const __nv_bfloat16* bl = g_wl + (long long)(wb_off + bn) * 4096;

    float acc[2][4][4];
#pragma unroll
    for (int i = 0; i < 2; i++)
#pragma unroll
        for (int j = 0; j < 4; j++)
#pragma unroll
            for (int q = 0; q < 4; q++) acc[i][j][q] = 0.f;

    auto load_stage = [&](uint32_t sbase, int k0) {
#pragma unroll
        for (int i = 0; i < 6; i++) {
            int s = tid + (i << 8);
            const __nv_bfloat16 *hsrc, *lsrc;
            uint32_t dst; int idx;
            if (s < 1024) { hsrc = ah; lsrc = al; dst = sbase;             idx = s; }
            else          { hsrc = bh; lsrc = bl; dst = sbase + HSM_B_OFF; idx = s - 1024; }
            int row = idx >> 3, g = idx & 7;
            const __nv_bfloat16* src = (g < 4 ? hsrc : lsrc)
                                     + (long long)row * 4096 + k0 + ((g & 3) << 3);
            cpa16(dst + row * 128 + ((g ^ (row & 7)) << 4), src, 16);
        }
        cpa_commit();
    };

    load_stage(smb, 0);

    const int a_row = (l & 15);
    const int a_half = l >> 4;
    const int b_rl = (l & 7) + ((l >> 4) << 3);
    const int b_half = (l >> 3) & 1;

    for (int c = 0; c < 128; c++) {
        cpa_wait0();
        __syncthreads();
        const uint32_t st = smb + (c & 1) * HSM_STAGE;
        if (c + 1 < 128) load_stage(smb + ((c + 1) & 1) * HSM_STAGE, (c + 1) << 5);

#pragma unroll
        for (int ks = 0; ks < 2; ks++) {
            uint32_t ahf[2][4], alf[2][4], bhf[2][4], blf[2][4];
#pragma unroll
            for (int mt = 0; mt < 2; mt++) {
                int row = (wm << 5) + (mt << 4) + a_row;
                int gh = (ks << 1) + a_half;
                uint32_t base = st + row * 128;
                ldsm4(ahf[mt], base + ((gh ^ (row & 7)) << 4));
                int gl = gh + 4;
                ldsm4(alf[mt], base + ((gl ^ (row & 7)) << 4));
            }
#pragma unroll
            for (int np = 0; np < 2; np++) {
                int row = (wn << 5) + (np << 4) + b_rl;
                int gh = (ks << 1) + b_half;
                uint32_t base = st + HSM_B_OFF + row * 128;
                ldsm4(bhf[np], base + ((gh ^ (row & 7)) << 4));
                int gl = gh + 4;
                ldsm4(blf[np], base + ((gl ^ (row & 7)) << 4));
            }
#pragma unroll
            for (int mt = 0; mt < 2; mt++)
#pragma unroll
                for (int np = 0; np < 2; np++)
#pragma unroll
                    for (int hh = 0; hh < 2; hh++) {
                        float* at = acc[mt][(np << 1) + hh];
                        mma16816(at, ahf[mt], &bhf[np][hh << 1]);
                        mma16816(at, ahf[mt], &blf[np][hh << 1]);
                        mma16816(at, alf[mt], &bhf[np][hh << 1]);
                    }
        }
        __syncthreads();
    }

#pragma unroll
    for (int mt = 0; mt < 2; mt++) {
#pragma unroll
        for (int nt = 0; nt < 4; nt++) {
            long long r0 = bm + (wm << 5) + (mt << 4) + (l >> 2);
            int col = bn + (wn << 5) + (nt << 3) + ((l & 3) << 1);
            float* cp = C + r0 * ldc + col;
            *(float2*)cp             = make_float2(acc[mt][nt][0], acc[mt][nt][1]);
            *(float2*)(cp + 8 * ldc) = make_float2(acc[mt][nt][2], acc[mt][nt][3]);
        }
    }
}

// ---------------- RoPE + rearrange ----------------
__global__ __launch_bounds__(256) void rope_qk(
    const float* __restrict__ pbuf, const float* __restrict__ fc, const float* __restrict__ fs)
{
    int i = blockIdx.x * blockDim.x + threadIdx.x;
    const int TOT = B_ * N_ * (H_ + HK_) * 64;
    if (i >= TOT) return;
    int pr   = i & 63;
    int head = (i >> 6) % (H_ + HK_);
    int bn   = (i >> 6) / (H_ + HK_);
    int n    = bn % N_;
    int b    = bn / N_;
    float c = fc[n * 64 + pr];
    float s = fs[n * 64 + pr];
    const float* row = pbuf + (long long)(b * N_ + n) * PCOLS;
    if (head < H_) {
        float a  = row[head * DH_ + 2 * pr];
        float bb = row[head * DH_ + 2 * pr + 1];
        float* q = g_q + ((long long)(b * H_ + head) * N_ + n) * DH_ + 2 * pr;
        q[0] = (a * c - bb * s) * SCALE;
        q[1] = (a * s + bb * c) * SCALE;
    } else {
        int hk = head - H_;
        float a  = row[H_ * DH_ + hk * DH_ + 2 * pr];
        float bb = row[H_ * DH_ + hk * DH_ + 2 * pr + 1];
        float* k = g_k + ((long long)(b * HK_ + hk) * N_ + n) * DH_ + 2 * pr;
        k[0] = a * c - bb * s;
        k[1] = a * s + bb * c;
    }
}

__global__ __launch_bounds__(256) void copy_v(const float* __restrict__ pbuf)
{
    int i = blockIdx.x * blockDim.x + threadIdx.x;
    if (i >= B_ * HK_ * N_ * DH_) return;
    int d  = i & 127;
    int n  = (i >> 7) & 15;
    int hk = (i >> 11) & 7;
    int b  = i >> 14;
    g_v[i] = pbuf[(long long)(b * N_ + n) * PCOLS + (H_ + HK_) * DH_ + hk * DH_ + d];
}

// ---------------- K cache -> fp16 [bhk][t][d] ----------------
__global__ __launch_bounds__(256) void conv_k(
    const float* __restrict__ cache_k, const int* __restrict__ sp, int ctx, int Tpad)
{
    int i = blockIdx.x * blockDim.x + threadIdx.x;
    int d4  = i & 31;
    int t   = (i >> 5) % Tpad;
    int bhk = i / (Tpad << 5);
    if (bhk >= 128) return;
    const int start = sp[0], tend = start + N_;
    float4 v;
    if (t < start)
        v = *(const float4*)(cache_k + ((long long)bhk * ctx + t) * DH_ + (d4 << 2));
    else if (t < tend)
        v = *(const float4*)(g_k + ((long long)bhk * N_ + (t - start)) * DH_ + (d4 << 2));
    else
        v = make_float4(0.f, 0.f, 0.f, 0.f);
    long long o = ((long long)bhk * Tpad + t) * 128 + (d4 << 2);
    *(uint2*)(g_kf + o) = make_uint2(cvth2(v.y, v.x), cvth2(v.w, v.z));
}

// ---------------- V cache -> fp16 transposed [bhk][d][t] ----------------
__global__ __launch_bounds__(256) void conv_vt(
    const float* __restrict__ cache_v, const int* __restrict__ sp, int ctx, int Tpad)
{
    __shared__ float ts[32][33];
    const int bhk = blockIdx.x, tb = blockIdx.y << 5, db = blockIdx.z << 5;
    const int tx = threadIdx.x & 31, ty = threadIdx.x >> 5;
    const int start = sp[0], tend = start + N_;
#pragma unroll
    for (int i = 0; i < 4; i++) {
        int t = tb + ty + (i << 3);
        float v;
        if (t < start)
            v = cache_v[((long long)bhk * ctx + t) * DH_ + db + tx];
        else if (t < tend)
            v = g_v[((long long)bhk * N_ + (t - start)) * DH_ + db + tx];
        else
            v = 0.f;
        ts[ty + (i << 3)][tx] = v;
    }
    __syncthreads();
#pragma unroll
    for (int i = 0; i < 4; i++) {
        int d = db + ty + (i << 3);
        g_vt[((long long)bhk * 128 + d) * Tpad + tb + tx] =
            __float2half(ts[tx][ty + (i << 3)]);
    }
}

// ---------------- attn: fp16 QK + fp16 PV; 3-stage pipeline; 8 kv-splits ----------------
#define ASM_Q   0
#define ASM_ST  16384
#define ASM_STRIDE 32768
#define ASM_TOT (16384 + 3 * 32768)

__global__ __launch_bounds__(256, 1) void attn(const int* __restrict__ sp, int Tpad)
{
    extern __shared__ char smr[];
    const int tid = threadIdx.x;
    const int l = tid & 31, w = tid >> 5;
    const int wm = w >> 1, wn = w & 1;
    const int bhk = blockIdx.x;
    const int ks  = blockIdx.y;          // 0..7
    const int start = sp[0];
    const int tend  = start + N_;
    const uint32_t smb = (uint32_t)__cvta_generic_to_shared(smr);

    const float* qbase = g_q + ((long long)(bhk >> 3) * H_ + (bhk & 7) * REP_) * N_ * DH_;
#pragma unroll
    for (int i = 0; i < 4; i++) {
        int j = tid + (i << 8);
        int row = j >> 4, g = j & 15;
        const float* src = qbase + row * 128 + (g << 3);
        float4 f0 = *(const float4*)src;
        float4 f1 = *(const float4*)(src + 4);
        uint32_t off = row * 256 + ((g ^ (row & 7)) << 4);
        *(uint4*)(smr + ASM_Q + off) = make_uint4(
            cvth2(f0.y, f0.x), cvth2(f0.w, f0.z), cvth2(f1.y, f1.x), cvth2(f1.w, f1.z));
    }

    auto load_stage = [&](uint32_t sbase, int t0) {
#pragma unroll
        for (int i = 0; i < 8; i++) {
            int s = tid + (i << 8);
            if (s < 1024) {
                int row = s >> 4, g = s & 15;
                const __half* src = g_kf
                    + ((long long)bhk * Tpad + t0 + row) * 128 + (g << 3);
                cpa16(sbase + row * 256 + ((g ^ (row & 7)) << 4), src, 16);
            } else {
                int idx = s - 1024;
                int row = idx >> 3, g = idx & 7;
                const __half* src = g_vt
                    + ((long long)bhk * 128 + row) * Tpad + t0 + (g << 3);
                cpa16(sbase + 16384 + row * 128 + ((g ^ (row & 7)) << 4), src, 16);
            }
        }
        cpa_commit();
    };

    const int nc = (tend - ks * 64 + 511) >> 9;
    load_stage(smb + ASM_ST, ks * 64);
    if (nc > 1) load_stage(smb + ASM_ST + ASM_STRIDE, ks * 64 + 512);

    float oacc[16][4];
#pragma unroll
    for (int i = 0; i < 16; i++)
#pragma unroll
        for (int q = 0; q < 4; q++) oacc[i][q] = 0.f;
    float lsumA = 0.f, lsumB = 0.f;
    const int limA = start + (l >> 2);
    const int limB = limA + 8;

    const int a_row = l & 15, a_half = l >> 4;
    const int b_rl = (l & 7) + ((l >> 4) << 3);
    const int b_half = (l >> 3) & 1;
    const int tg = l & 3;

    for (int ci = 0; ci < nc; ci++) {
        const int t0 = ks * 64 + (ci << 9);
        if (ci + 2 <= nc) cpa_wait1(); else cpa_wait0();
        __syncthreads();
        const uint32_t st = smb + ASM_ST + (ci % 3) * ASM_STRIDE;
        if (ci + 2 < nc)
            load_stage(smb + ASM_ST + ((ci + 2) % 3) * ASM_STRIDE, t0 + 1024);

        float sacc[4][4];
#pragma unroll
        for (int i = 0; i < 4; i++)
#pragma unroll
            for (int q = 0; q < 4; q++) sacc[i][q] = 0.f;
#pragma unroll
        for (int kk = 0; kk < 8; kk++) {
            uint32_t ah[4], bh[2][4];
            {
                int row = (wm << 4) + a_row;
                int g = (kk << 1) + a_half;
                ldsm4(ah, smb + ASM_Q + row * 256 + ((g ^ (row & 7)) << 4));
            }
#pragma unroll
            for (int np = 0; np < 2; np++) {
                int row = (wn << 5) + (np << 4) + b_rl;
                int g = (kk << 1) + b_half;
                ldsm4(bh[np], st + row * 256 + ((g ^ (row & 7)) << 4));
            }
#pragma unroll
            for (int np = 0; np < 2; np++)
#pragma unroll
                for (int hh = 0; hh < 2; hh++)
                    mma16816h(sacc[(np << 1) + hh], ah, &bh[np][hh << 1]);
        }

        uint32_t pa[2][4];
#pragma unroll
        for (int nt = 0; nt < 4; nt++) {
            int tb = t0 + (wn << 5) + (nt << 3) + (tg << 1);
            float p0 = (tb     <= limA) ? __expf(sacc[nt][0]) : 0.f;
            float p1 = (tb + 1 <= limA) ? __expf(sacc[nt][1]) : 0.f;
            float p2 = (tb     <= limB) ? __expf(sacc[nt][2]) : 0.f;
            float p3 = (tb + 1 <= limB) ? __expf(sacc[nt][3]) : 0.f;
            lsumA += p0 + p1;
            lsumB += p2 + p3;
            int kt = nt >> 1, hf = nt & 1;
            pa[kt][(hf << 1) + 0] = cvth2(p1, p0);
            pa[kt][(hf << 1) + 1] = cvth2(p3, p2);
        }

#pragma unroll
        for (int kt = 0; kt < 2; kt++) {
#pragma unroll
            for (int np = 0; np < 8; np++) {
                int row = (np << 4) + b_rl;
                int g = (wn << 2) + (kt << 1) + b_half;
                uint32_t bv[4];
                ldsm4(bv, st + 16384 + row * 128 + ((g ^ (row & 7)) << 4));
                mma16816h(oacc[(np << 1) + 0], pa[kt], &bv[0]);
                mma16816h(oacc[(np << 1) + 1], pa[kt], &bv[2]);
            }
        }
    }

#pragma unroll
    for (int m = 1; m < 4; m <<= 1) {
        lsumA += __shfl_xor_sync(0xffffffffu, lsumA, m);
        lsumB += __shfl_xor_sync(0xffffffffu, lsumB, m);
    }

    const int spn = (ks << 1) + wn;
    const long long pb = ((long long)bhk * NSP2 + spn) * 64;
    if (tg == 0) {
        g_pl[pb + (wm << 4) + (l >> 2)]     = lsumA;
        g_pl[pb + (wm << 4) + (l >> 2) + 8] = lsumB;
    }
#pragma unroll
    for (int nt = 0; nt < 16; nt++) {
        long long r0 = pb + (wm << 4) + (l >> 2);
        int d = (nt << 3) + (tg << 1);
        *(float2*)(g_pacc + r0 * 128 + d)       = make_float2(oacc[nt][0], oacc[nt][1]);
        *(float2*)(g_pacc + (r0 + 8) * 128 + d) = make_float2(oacc[nt][2], oacc[nt][3]);
    }
}

// ---------------- combine partials -> zh/zl (bf16 split fused) ----------------
__global__ __launch_bounds__(256) void attn_combine(
    __nv_bfloat16* __restrict__ zh, __nv_bfloat16* __restrict__ zl)
{
    int idx = blockIdx.x * blockDim.x + threadIdx.x;
    if (idx >= 128 * 64 * 128) return;
    int d    = idx & 127;
    int row  = (idx >> 7) & 63;
    int bhk  = idx >> 13;
    float a = 0.f, lv = 0.f;
#pragma unroll
    for (int spn = 0; spn < NSP2; spn++) {
        long long base = ((long long)bhk * NSP2 + spn) * 64 + row;
        a  += g_pacc[base * 128 + d];
        lv += g_pl[base];
    }
    int r = row >> 4, n = row & 15;
    int b = bhk >> 3, hk = bhk & 7;
    float v = a / lv;
    __nv_bfloat16 h = __float2bfloat16(v);
    long long o = (long long)(b * N_ + n) * D_ + (hk * REP_ + r) * DH_ + d;
    zh[o] = h;
    zl[o] = __float2bfloat16(v - __bfloat162float(h));
}

// ---------------- launch ----------------
extern "C" void kernel_launch(void* const* d_in, const int* in_sizes, int n_in,
                              void* d_out, int out_size)
{
    const float* x  = (const float*)d_in[0];
    const float* fc = (const float*)d_in[1];
    const float* fs = (const float*)d_in[2];
    const float* ck = (const float*)d_in[4];
    const float* cv = (const float*)d_in[5];
    const float* wq = (const float*)d_in[6];
    const float* wk = (const float*)d_in[7];
    const float* wv = (const float*)d_in[8];
    const float* wo = (const float*)d_in[9];
    const int*   sp = (const int*)d_in[10];
    float* out = (float*)d_out;

    int ctx  = in_sizes[4] / (B_ * HK_ * DH_);
    int T    = in_sizes[3] / N_;
    int Tpad = ((T + 63) / 64) * 64;
    if (Tpad > TPC) Tpad = TPC;

    float* pbuf; cudaGetSymbolAddress((void**)&pbuf, g_pbuf);
    __nv_bfloat16 *xh, *xl, *zh, *zl;
    cudaGetSymbolAddress((void**)&xh, g_xh);
    cudaGetSymbolAddress((void**)&xl, g_xl);
    cudaGetSymbolAddress((void**)&zh, g_zh);
    cudaGetSymbolAddress((void**)&zl, g_zl);

    dim3 blk(256);

    conv_w<<<dim3(128, 320), blk>>>(wq, wk, wv, wo);
    conv_split<<<(256 * 4096 + 255) / 256, blk>>>(x, xh, xl, 256 * 4096);

    cudaFuncSetAttribute(hgemm, cudaFuncAttributeMaxDynamicSharedMemorySize, HSM_TOT);
    hgemm<<<dim3(96, 2), blk, HSM_TOT>>>(xh, xl, 0, pbuf, PCOLS);

    rope_qk<<<(B_ * N_ * (H_ + HK_) * 64 + 255) / 256, blk>>>(pbuf, fc, fs);
    copy_v<<<(B_ * HK_ * N_ * DH_ + 255) / 256, blk>>>(pbuf);

    conv_k<<<(128 * Tpad * 32 + 255) / 256, blk>>>(ck, sp, ctx, Tpad);
    conv_vt<<<dim3(128, Tpad / 32, 4), blk>>>(cv, sp, ctx, Tpad);

    cudaFuncSetAttribute(attn, cudaFuncAttributeMaxDynamicSharedMemorySize, ASM_TOT);
    attn<<<dim3(128, 8), blk, ASM_TOT>>>(sp, Tpad);
    attn_combine<<<(128 * 64 * 128 + 255) / 256, blk>>>(zh, zl);

    hgemm<<<dim3(64, 2), blk, HSM_TOT>>>(zh, zl, 6144, out, D_);
}

// round 15
// speedup vs baseline: 1.0965x; 1.0157x over previous
#include <cuda_runtime.h>
#include <cuda_bf16.h>
#include <cuda_fp16.h>
#include <cstdint>

#define B_    16
#define N_    16
#define D_    4096
#define H_    32
#define HK_   8
#define REP_  4
#define DH_   128
#define PCOLS 6144
#define SCALE 0.08838834764831844f
#define WB_ROWS 10240
#define TPC   2112
#define NSP2  16

typedef unsigned long long u64;

__device__ __forceinline__ void cpa16(uint32_t dst, const void* src, int sz) {
    asm volatile("cp.async.cg.shared.global [%0], [%1], 16, %2;"
                 :: "r"(dst), "l"(src), "r"(sz));
}
__device__ __forceinline__ void cpa_commit() {
    asm volatile("cp.async.commit_group;" ::: "memory");
}
__device__ __forceinline__ void cpa_wait0() {
    asm volatile("cp.async.wait_group 0;" ::: "memory");
}
__device__ __forceinline__ void cpa_wait1() {
    asm volatile("cp.async.wait_group 1;" ::: "memory");
}
__device__ __forceinline__ void ldsm4(uint32_t* r, uint32_t addr) {
    asm volatile("ldmatrix.sync.aligned.m8n8.x4.shared.b16 {%0,%1,%2,%3}, [%4];"
                 : "=r"(r[0]), "=r"(r[1]), "=r"(r[2]), "=r"(r[3]) : "r"(addr));
}
__device__ __forceinline__ void ldsm4t(uint32_t* r, uint32_t addr) {
    asm volatile("ldmatrix.sync.aligned.m8n8.x4.trans.shared.b16 {%0,%1,%2,%3}, [%4];"
                 : "=r"(r[0]), "=r"(r[1]), "=r"(r[2]), "=r"(r[3]) : "r"(addr));
}
__device__ __forceinline__ void mma16816(float* c, const uint32_t* a, const uint32_t* b) {
    asm volatile("mma.sync.aligned.m16n8k16.row.col.f32.bf16.bf16.f32 "
        "{%0,%1,%2,%3}, {%4,%5,%6,%7}, {%8,%9}, {%0,%1,%2,%3};"
        : "+f"(c[0]), "+f"(c[1]), "+f"(c[2]), "+f"(c[3])
        : "r"(a[0]), "r"(a[1]), "r"(a[2]), "r"(a[3]), "r"(b[0]), "r"(b[1]));
}
__device__ __forceinline__ void mma16816h(float* c, const uint32_t* a, const uint32_t* b) {
    asm volatile("mma.sync.aligned.m16n8k16.row.col.f32.f16.f16.f32 "
        "{%0,%1,%2,%3}, {%4,%5,%6,%7}, {%8,%9}, {%0,%1,%2,%3};"
        : "+f"(c[0]), "+f"(c[1]), "+f"(c[2]), "+f"(c[3])
        : "r"(a[0]), "r"(a[1]), "r"(a[2]), "r"(a[3]), "r"(b[0]), "r"(b[1]));
}
__device__ __forceinline__ uint32_t cvt2(float hi, float lo) {
    uint32_t r; asm("cvt.rn.bf16x2.f32 %0, %1, %2;" : "=r"(r) : "f"(hi), "f"(lo));
    return r;
}
__device__ __forceinline__ uint32_t cvth2(float hi, float lo) {
    uint32_t r; asm("cvt.rn.f16x2.f32 %0, %1, %2;" : "=r"(r) : "f"(hi), "f"(lo));
    return r;
}
__device__ __forceinline__ void split2(float a, float b, uint32_t& h, uint32_t& lo) {
    h = cvt2(b, a);
    float ha = __uint_as_float(h << 16);
    float hb = __uint_as_float(h & 0xffff0000u);
    lo = cvt2(b - hb, a - ha);
}

// ---------------- scratch ----------------
__device__ float g_pbuf[256 * PCOLS];
__device__ float g_q[B_ * H_ * N_ * DH_];
__device__ float g_k[B_ * HK_ * N_ * DH_];
__device__ float g_v[B_ * HK_ * N_ * DH_];
__device__ float g_pacc[128 * NSP2 * 64 * 128];
__device__ float g_pl[128 * NSP2 * 64];
__device__ __align__(16) __nv_bfloat16 g_wh[WB_ROWS * 4096];
__device__ __align__(16) __nv_bfloat16 g_wl[WB_ROWS * 4096];
__device__ __align__(16) __nv_bfloat16 g_xh[256 * 4096];
__device__ __align__(16) __nv_bfloat16 g_xl[256 * 4096];
__device__ __align__(16) __nv_bfloat16 g_zh[256 * 4096];
__device__ __align__(16) __nv_bfloat16 g_zl[256 * 4096];
__device__ __align__(16) __half       g_kf[128 * TPC * 128];   // fp16 K [bhk][t][d]
__device__ __align__(16) __half       g_vf[128 * TPC * 128];   // fp16 V [bhk][t][d]

// ---------------- weight transpose + bf16 split (register-gather, vectorized) --
// thread: 4 n-rows x 8 k. CTA: 128 n x 64 k. Grid (4096/64, 10240/128).
__global__ __launch_bounds__(256) void conv_w(
    const float* __restrict__ wq, const float* __restrict__ wk,
    const float* __restrict__ wv, const float* __restrict__ wo)
{
    const int l = threadIdx.x & 31, w = threadIdx.x >> 5;
    const int k0 = (blockIdx.x << 6) + (w << 3);
    const int n0 = (blockIdx.y << 7) + (l << 2);

    const float* src; int nn, pitch;
    if (n0 < 4096)      { src = wq; nn = n0;        pitch = 4096; }
    else if (n0 < 5120) { src = wk; nn = n0 - 4096; pitch = 1024; }
    else if (n0 < 6144) { src = wv; nn = n0 - 5120; pitch = 1024; }
    else                { src = wo; nn = n0 - 6144; pitch = 4096; }

    float4 v[8];
#pragma unroll
    for (int j = 0; j < 8; j++)
        v[j] = *(const float4*)(src + (long long)(k0 + j) * pitch + nn);
    const float* vp = (const float*)v;

#pragma unroll
    for (int n = 0; n < 4; n++) {
        uint32_t hi[4], lo[4];
#pragma unroll
        for (int kp = 0; kp < 4; kp++)
            split2(vp[(2 * kp) * 4 + n], vp[(2 * kp + 1) * 4 + n], hi[kp], lo[kp]);
        long long o = (long long)(n0 + n) * 4096 + k0;
        *(uint4*)(g_wh + o) = make_uint4(hi[0], hi[1], hi[2], hi[3]);
        *(uint4*)(g_wl + o) = make_uint4(lo[0], lo[1], lo[2], lo[3]);
    }
}

// ---------------- activation bf16 split (vectorized x4) ----------------
__global__ __launch_bounds__(256) void conv_split(
    const float* __restrict__ src, __nv_bfloat16* __restrict__ hh,
    __nv_bfloat16* __restrict__ ll, int n4)
{
    int i = blockIdx.x * blockDim.x + threadIdx.x;
    if (i >= n4) return;
    float4 f = *(const float4*)(src + (i << 2));
    uint32_t h0, l0, h1, l1;
    split2(f.x, f.y, h0, l0);
    split2(f.z, f.w, h1, l1);
    *(uint2*)(hh + (i << 2)) = make_uint2(h0, h1);
    *(uint2*)(ll + (i << 2)) = make_uint2(l0, l1);
}

// ---------------- HMMA bf16x3 GEMM: 128x64 tiles (unchanged R12 config) --------
#define HSM_STAGE 24576
#define HSM_B_OFF 16384
#define HSM_TOT   49152

__global__ __launch_bounds__(256) void hgemm(
    const __nv_bfloat16* __restrict__ Ah, const __nv_bfloat16* __restrict__ Al,
    int wb_off, float* __restrict__ C, int ldc)
{
    extern __shared__ char smr[];
    const int tid = threadIdx.x;
    const int l = tid & 31, w = tid >> 5;
    const int wm = w >> 1, wn = w & 1;
    const int bn = blockIdx.x << 6, bm = blockIdx.y << 7;
    const uint32_t smb = (uint32_t)__cvta_generic_to_shared(smr);

    const __nv_bfloat16* ah = Ah + (long long)bm * 4096;
    const __nv_bfloat16* al = Al + (long long)bm * 4096;
    const __nv_bfloat16* bh = g_wh + (long long)(wb_off + bn) * 4096;
    const __nv_bfloat16* bl = g_wl + (long long)(wb_off + bn) * 4096;

    float acc[2][4][4];
#pragma unroll
    for (int i = 0; i < 2; i++)
#pragma unroll
        for (int j = 0; j < 4; j++)
#pragma unroll
            for (int q = 0; q < 4; q++) acc[i][j][q] = 0.f;

    auto load_stage = [&](uint32_t sbase, int k0) {
#pragma unroll
        for (int i = 0; i < 6; i++) {
            int s = tid + (i << 8);
            const __nv_bfloat16 *hsrc, *lsrc;
            uint32_t dst; int idx;
            if (s < 1024) { hsrc = ah; lsrc = al; dst = sbase;             idx = s; }
            else          { hsrc = bh; lsrc = bl; dst = sbase + HSM_B_OFF; idx = s - 1024; }
            int row = idx >> 3, g = idx & 7;
            const __nv_bfloat16* src = (g < 4 ? hsrc : lsrc)
                                     + (long long)row * 4096 + k0 + ((g & 3) << 3);
            cpa16(dst + row * 128 + ((g ^ (row & 7)) << 4), src, 16);
        }
        cpa_commit();
    };

    load_stage(smb, 0);

    const int a_row = (l & 15);
    const int a_half = l >> 4;
    const int b_rl = (l & 7) + ((l >> 4) << 3);
    const int b_half = (l >> 3) & 1;

    for (int c = 0; c < 128; c++) {
        cpa_wait0();
        __syncthreads();
        const uint32_t st = smb + (c & 1) * HSM_STAGE;
        if (c + 1 < 128) load_stage(smb + ((c + 1) & 1) * HSM_STAGE, (c + 1) << 5);

#pragma unroll
        for (int ks = 0; ks < 2; ks++) {
            uint32_t ahf[2][4], alf[2][4], bhf[2][4], blf[2][4];
#pragma unroll
            for (int mt = 0; mt < 2; mt++) {
                int row = (wm << 5) + (mt << 4) + a_row;
                int gh = (ks << 1) + a_half;
                uint32_t base = st + row * 128;
                ldsm4(ahf[mt], base + ((gh ^ (row & 7)) << 4));
                int gl = gh + 4;
                ldsm4(alf[mt], base + ((gl ^ (row & 7)) << 4));
            }
#pragma unroll
            for (int np = 0; np < 2; np++) {
                int row = (wn << 5) + (np << 4) + b_rl;
                int gh = (ks << 1) + b_half;
                uint32_t base = st + HSM_B_OFF + row * 128;
                ldsm4(bhf[np], base + ((gh ^ (row & 7)) << 4));
                int gl = gh + 4;
                ldsm4(blf[np], base + ((gl ^ (row & 7)) << 4));
            }
#pragma unroll
            for (int mt = 0; mt < 2; mt++)
#pragma unroll
                for (int np = 0; np < 2; np++)
#pragma unroll
                    for (int hh = 0; hh < 2; hh++) {
                        float* at = acc[mt][(np << 1) + hh];
                        mma16816(at, ahf[mt], &bhf[np][hh << 1]);
                        mma16816(at, ahf[mt], &blf[np][hh << 1]);
                        mma16816(at, alf[mt], &bhf[np][hh << 1]);
                    }
        }
        __syncthreads();
    }

#pragma unroll
    for (int mt = 0; mt < 2; mt++) {
#pragma unroll
        for (int nt = 0; nt < 4; nt++) {
            long long r0 = bm + (wm << 5) + (mt << 4) + (l >> 2);
            int col = bn + (wn << 5) + (nt << 3) + ((l & 3) << 1);
            float* cp = C + r0 * ldc + col;
            *(float2*)cp             = make_float2(acc[mt][nt][0], acc[mt][nt][1]);
            *(float2*)(cp + 8 * ldc) = make_float2(acc[mt][nt][2], acc[mt][nt][3]);
        }
    }
}

// ---------------- RoPE + rearrange ----------------
__global__ __launch_bounds__(256) void rope_qk(
    const float* __restrict__ pbuf, const float* __restrict__ fc, const float* __restrict__ fs)
{
    int i = blockIdx.x * blockDim.x + threadIdx.x;
    const int TOT = B_ * N_ * (H_ + HK_) * 64;
    if (i >= TOT) return;
    int pr   = i & 63;
    int head = (i >> 6) % (H_ + HK_);
    int bn   = (i >> 6) / (H_ + HK_);
    int n    = bn % N_;
    int b    = bn / N_;
    float c = fc[n * 64 + pr];
    float s = fs[n * 64 + pr];
    const float* row = pbuf + (long long)(b * N_ + n) * PCOLS;
    if (head < H_) {
        float a  = row[head * DH_ + 2 * pr];
        float bb = row[head * DH_ + 2 * pr + 1];
        float* q = g_q + ((long long)(b * H_ + head) * N_ + n) * DH_ + 2 * pr;
        q[0] = (a * c - bb * s) * SCALE;
        q[1] = (a * s + bb * c) * SCALE;
    } else {
        int hk = head - H_;
        float a  = row[H_ * DH_ + hk * DH_ + 2 * pr];
        float bb = row[H_ * DH_ + hk * DH_ + 2 * pr + 1];
        float* k = g_k + ((long long)(b * HK_ + hk) * N_ + n) * DH_ + 2 * pr;
        k[0] = a * c - bb * s;
        k[1] = a * s + bb * c;
    }
}

__global__ __launch_bounds__(256) void copy_v(const float* __restrict__ pbuf)
{
    int i = blockIdx.x * blockDim.x + threadIdx.x;
    if (i >= B_ * HK_ * N_ * DH_) return;
    int d  = i & 127;
    int n  = (i >> 7) & 15;
    int hk = (i >> 11) & 7;
    int b  = i >> 14;
    g_v[i] = pbuf[(long long)(b * N_ + n) * PCOLS + (H_ + HK_) * DH_ + hk * DH_ + d];
}

// ---------------- K+V cache -> fp16 [bhk][t][d] (elementwise, 8 elems/thread) --
__global__ __launch_bounds__(256) void conv_kv(
    const float* __restrict__ cache_k, const float* __restrict__ cache_v,
    const int* __restrict__ sp, int ctx, int Tpad)
{
    int i = blockIdx.x * blockDim.x + threadIdx.x;
    if (i >= 128 * Tpad * 16) return;
    int g8  = i & 15;
    int t   = (i >> 4) % Tpad;
    int bhk = i / (Tpad << 4);
    const int start = sp[0], tend = start + N_;
    const int sel = blockIdx.y;
    const float* cache = sel ? cache_v : cache_k;
    const float* fresh = sel ? g_v : g_k;
    __half* dst = sel ? g_vf : g_kf;

    float4 v0, v1;
    if (t < start) {
        const float* p = cache + ((long long)bhk * ctx + t) * DH_ + (g8 << 3);
        v0 = *(const float4*)p; v1 = *(const float4*)(p + 4);
    } else if (t < tend) {
        const float* p = fresh + ((long long)bhk * N_ + (t - start)) * DH_ + (g8 << 3);
        v0 = *(const float4*)p; v1 = *(const float4*)(p + 4);
    } else {
        v0 = make_float4(0.f, 0.f, 0.f, 0.f); v1 = v0;
    }
    long long o = ((long long)bhk * Tpad + t) * 128 + (g8 << 3);
    *(uint4*)(dst + o) = make_uint4(cvth2(v0.y, v0.x), cvth2(v0.w, v0.z),
                                    cvth2(v1.y, v1.x), cvth2(v1.w, v1.z));
}

// ---------------- attn: fp16 QK + fp16 PV (V via trans-ldmatrix) ----------------
#define ASM_Q   0
#define ASM_ST  16384
#define ASM_STRIDE 32768
#define ASM_TOT (16384 + 3 * 32768)

__global__ __launch_bounds__(256, 1) void attn(const int* __restrict__ sp, int Tpad)
{
    extern __shared__ char smr[];
    const int tid = threadIdx.x;
    const int l = tid & 31, w = tid >> 5;
    const int wm = w >> 1, wn = w & 1;
    const int bhk = blockIdx.x;
    const int ks  = blockIdx.y;
    const int start = sp[0];
    const int tend  = start + N_;
    const uint32_t smb = (uint32_t)__cvta_generic_to_shared(smr);

    const float* qbase = g_q + ((long long)(bhk >> 3) * H_ + (bhk & 7) * REP_) * N_ * DH_;
#pragma unroll
    for (int i = 0; i < 4; i++) {
        int j = tid + (i << 8);
        int row = j >> 4, g = j & 15;
        const float* src = qbase + row * 128 + (g << 3);
        float4 f0 = *(const float4*)src;
        float4 f1 = *(const float4*)(src + 4);
        uint32_t off = row * 256 + ((g ^ (row & 7)) << 4);
        *(uint4*)(smr + ASM_Q + off) = make_uint4(
            cvth2(f0.y, f0.x), cvth2(f0.w, f0.z), cvth2(f1.y, f1.x), cvth2(f1.w, f1.z));
    }

    // stage: K [t][d] 64x256B + V [t][d] 64x256B, both swizzled identically
    auto load_stage = [&](uint32_t sbase, int t0) {
#pragma unroll
        for (int i = 0; i < 8; i++) {
            int s = tid + (i << 8);
            int sel = s >> 10, idx = s & 1023;
            int row = idx >> 4, g = idx & 15;
            const __half* src = (sel ? g_vf : g_kf)
                + ((long long)bhk * Tpad + t0 + row) * 128 + (g << 3);
            cpa16(sbase + sel * 16384 + row * 256 + ((g ^ (row & 7)) << 4), src, 16);
        }
        cpa_commit();
    };

    const int nc = (tend - ks * 64 + 511) >> 9;
    load_stage(smb + ASM_ST, ks * 64);
    if (nc > 1) load_stage(smb + ASM_ST + ASM_STRIDE, ks * 64 + 512);

    float oacc[16][4];
#pragma unroll
    for (int i = 0; i < 16; i++)
#pragma unroll
        for (int q = 0; q < 4; q++) oacc[i][q] = 0.f;
    float lsumA = 0.f, lsumB = 0.f;
    const int limA = start + (l >> 2);
    const int limB = limA + 8;

    const int a_row = l & 15, a_half = l >> 4;
    const int b_rl = (l & 7) + ((l >> 4) << 3);
    const int b_half = (l >> 3) & 1;
    const int tg = l & 3;
    const int v_tl = (l & 7) + (((l >> 3) & 1) << 3);   // t-row within 16 for trans ldsm
    const int v_gh = l >> 4;                            // d-granule select (+0/+1)

    for (int ci = 0; ci < nc; ci++) {
        const int t0 = ks * 64 + (ci << 9);
        if (ci + 2 <= nc) cpa_wait1(); else cpa_wait0();
        __syncthreads();
        const uint32_t st = smb + ASM_ST + (ci % 3) * ASM_STRIDE;
        if (ci + 2 < nc)
            load_stage(smb + ASM_ST + ((ci + 2) % 3) * ASM_STRIDE, t0 + 1024);

        // S = Q K^T (fp16)
        float sacc[4][4];
#pragma unroll
        for (int i = 0; i < 4; i++)
#pragma unroll
            for (int q = 0; q < 4; q++) sacc[i][q] = 0.f;
#pragma unroll
        for (int kk = 0; kk < 8; kk++) {
            uint32_t ah[4], bh[2][4];
            {
                int row = (wm << 4) + a_row;
                int g = (kk << 1) + a_half;
                ldsm4(ah, smb + ASM_Q + row * 256 + ((g ^ (row & 7)) << 4));
            }
#pragma unroll
            for (int np = 0; np < 2; np++) {
                int row = (wn << 5) + (np << 4) + b_rl;
                int g = (kk << 1) + b_half;
                ldsm4(bh[np], st + row * 256 + ((g ^ (row & 7)) << 4));
            }
#pragma unroll
            for (int np = 0; np < 2; np++)
#pragma unroll
                for (int hh = 0; hh < 2; hh++)
                    mma16816h(sacc[(np << 1) + hh], ah, &bh[np][hh << 1]);
        }

        // exp + mask -> P fp16 A-fragments
        uint32_t pa[2][4];
#pragma unroll
        for (int nt = 0; nt < 4; nt++) {
            int tb = t0 + (wn << 5) + (nt << 3) + (tg << 1);
            float p0 = (tb     <= limA) ? __expf(sacc[nt][0]) : 0.f;
            float p1 = (tb + 1 <= limA) ? __expf(sacc[nt][1]) : 0.f;
            float p2 = (tb     <= limB) ? __expf(sacc[nt][2]) : 0.f;
            float p3 = (tb + 1 <= limB) ? __expf(sacc[nt][3]) : 0.f;
            lsumA += p0 + p1;
            lsumB += p2 + p3;
            int kt = nt >> 1, hf = nt & 1;
            pa[kt][(hf << 1) + 0] = cvth2(p1, p0);
            pa[kt][(hf << 1) + 1] = cvth2(p3, p2);
        }

        // out += P V ; V[t][d] via trans ldsm: B-frags for n(=d)-tiles
        const uint32_t stV = st + 16384;
#pragma unroll
        for (int kt = 0; kt < 2; kt++) {
            int trow = (wn << 5) + (kt << 4) + v_tl;
            uint32_t rbase = stV + trow * 256;
            int rsw = trow & 7;
#pragma unroll
            for (int np = 0; np < 8; np++) {
                int g = (np << 1) + v_gh;
                uint32_t bv[4];
                ldsm4t(bv, rbase + ((g ^ rsw) << 4));
                mma16816h(oacc[(np << 1) + 0], pa[kt], &bv[0]);
                mma16816h(oacc[(np << 1) + 1], pa[kt], &bv[2]);
            }
        }
    }

#pragma unroll
    for (int m = 1; m < 4; m <<= 1) {
        lsumA += __shfl_xor_sync(0xffffffffu, lsumA, m);
        lsumB += __shfl_xor_sync(0xffffffffu, lsumB, m);
    }

    const int spn = (ks << 1) + wn;
    const long long pb = ((long long)bhk * NSP2 + spn) * 64;
    if (tg == 0) {
        g_pl[pb + (wm << 4) + (l >> 2)]     = lsumA;
        g_pl[pb + (wm << 4) + (l >> 2) + 8] = lsumB;
    }
#pragma unroll
    for (int nt = 0; nt < 16; nt++) {
        long long r0 = pb + (wm << 4) + (l >> 2);
        int d = (nt << 3) + (tg << 1);
        *(float2*)(g_pacc + r0 * 128 + d)       = make_float2(oacc[nt][0], oacc[nt][1]);
        *(float2*)(g_pacc + (r0 + 8) * 128 + d) = make_float2(oacc[nt][2], oacc[nt][3]);
    }
}

// ---------------- combine partials -> zh/zl (vectorized x4) ----------------
__global__ __launch_bounds__(256) void attn_combine(
    __nv_bfloat16* __restrict__ zh, __nv_bfloat16* __restrict__ zl)
{
    int idx = blockIdx.x * blockDim.x + threadIdx.x;   // (bhk, row, d-quad)
    if (idx >= 128 * 64 * 32) return;
    int dq   = idx & 31;
    int row  = (idx >> 5) & 63;
    int bhk  = idx >> 11;
    int d0   = dq << 2;
    float4 a = make_float4(0.f, 0.f, 0.f, 0.f);
    float lv = 0.f;
#pragma unroll
    for (int spn = 0; spn < NSP2; spn++) {
        long long base = ((long long)bhk * NSP2 + spn) * 64 + row;
        float4 t = *(const float4*)(g_pacc + base * 128 + d0);
        a.x += t.x; a.y += t.y; a.z += t.z; a.w += t.w;
        lv += g_pl[base];
    }
    float inv = __frcp_rn(lv);
    float v0 = a.x * inv, v1 = a.y * inv, v2 = a.z * inv, v3 = a.w * inv;
    uint32_t h0, l0, h1, l1;
    split2(v0, v1, h0, l0);
    split2(v2, v3, h1, l1);
    int r = row >> 4, n = row & 15;
    int b = bhk >> 3, hk = bhk & 7;
    long long o = (long long)(b * N_ + n) * D_ + (hk * REP_ + r) * DH_ + d0;
    *(uint2*)(zh + o) = make_uint2(h0, h1);
    *(uint2*)(zl + o) = make_uint2(l0, l1);
}

// ---------------- launch ----------------
extern "C" void kernel_launch(void* const* d_in, const int* in_sizes, int n_in,
                              void* d_out, int out_size)
{
    const float* x  = (const float*)d_in[0];
    const float* fc = (const float*)d_in[1];
    const float* fs = (const float*)d_in[2];
    const float* ck = (const float*)d_in[4];
    const float* cv = (const float*)d_in[5];
    const float* wq = (const float*)d_in[6];
    const float* wk = (const float*)d_in[7];
    const float* wv = (const float*)d_in[8];
    const float* wo = (const float*)d_in[9];
    const int*   sp = (const int*)d_in[10];
    float* out = (float*)d_out;

    int ctx  = in_sizes[4] / (B_ * HK_ * DH_);
    int T    = in_sizes[3] / N_;
    int Tpad = ((T + 63) / 64) * 64;
    if (Tpad > TPC) Tpad = TPC;

    float* pbuf; cudaGetSymbolAddress((void**)&pbuf, g_pbuf);
    __nv_bfloat16 *xh, *xl, *zh, *zl;
    cudaGetSymbolAddress((void**)&xh, g_xh);
    cudaGetSymbolAddress((void**)&xl, g_xl);
    cudaGetSymbolAddress((void**)&zh, g_zh);
    cudaGetSymbolAddress((void**)&zl, g_zl);

    dim3 blk(256);

    conv_w<<<dim3(64, 80), blk>>>(wq, wk, wv, wo);
    conv_split<<<(256 * 1024 + 255) / 256, blk>>>(x, xh, xl, 256 * 1024);

    cudaFuncSetAttribute(hgemm, cudaFuncAttributeMaxDynamicSharedMemorySize, HSM_TOT);
    hgemm<<<dim3(96, 2), blk, HSM_TOT>>>(xh, xl, 0, pbuf, PCOLS);

    rope_qk<<<(B_ * N_ * (H_ + HK_) * 64 + 255) / 256, blk>>>(pbuf, fc, fs);
    copy_v<<<(B_ * HK_ * N_ * DH_ + 255) / 256, blk>>>(pbuf);

    conv_kv<<<dim3((128 * Tpad * 16 + 255) / 256, 2), blk>>>(ck, cv, sp, ctx, Tpad);

    cudaFuncSetAttribute(attn, cudaFuncAttributeMaxDynamicSharedMemorySize, ASM_TOT);
    attn<<<dim3(128, 8), blk, ASM_TOT>>>(sp, Tpad);
    attn_combine<<<(128 * 64 * 32 + 255) / 256, blk>>>(zh, zl);

    hgemm<<<dim3(64, 2), blk, HSM_TOT>>>(zh, zl, 6144, out, D_);
}

// round 16
// speedup vs baseline: 1.1256x; 1.0266x over previous
#include <cuda_runtime.h>
#include <cuda_bf16.h>
#include <cuda_fp16.h>
#include <cstdint>

#define B_    16
#define N_    16
#define D_    4096
#define H_    32
#define HK_   8
#define REP_  4
#define DH_   128
#define PCOLS 6144
#define SCALE 0.08838834764831844f
#define WB_ROWS 10240
#define TPC   2112
#define NSP2  16

typedef unsigned long long u64;

__device__ __forceinline__ void cpa16(uint32_t dst, const void* src, int sz) {
    asm volatile("cp.async.cg.shared.global [%0], [%1], 16, %2;"
                 :: "r"(dst), "l"(src), "r"(sz));
}
__device__ __forceinline__ void cpa_commit() {
    asm volatile("cp.async.commit_group;" ::: "memory");
}
__device__ __forceinline__ void cpa_wait0() {
    asm volatile("cp.async.wait_group 0;" ::: "memory");
}
__device__ __forceinline__ void cpa_wait1() {
    asm volatile("cp.async.wait_group 1;" ::: "memory");
}
__device__ __forceinline__ void ldsm4(uint32_t* r, uint32_t addr) {
    asm volatile("ldmatrix.sync.aligned.m8n8.x4.shared.b16 {%0,%1,%2,%3}, [%4];"
                 : "=r"(r[0]), "=r"(r[1]), "=r"(r[2]), "=r"(r[3]) : "r"(addr));
}
__device__ __forceinline__ void ldsm4t(uint32_t* r, uint32_t addr) {
    asm volatile("ldmatrix.sync.aligned.m8n8.x4.trans.shared.b16 {%0,%1,%2,%3}, [%4];"
                 : "=r"(r[0]), "=r"(r[1]), "=r"(r[2]), "=r"(r[3]) : "r"(addr));
}
__device__ __forceinline__ void mma16816(float* c, const uint32_t* a, const uint32_t* b) {
    asm volatile("mma.sync.aligned.m16n8k16.row.col.f32.bf16.bf16.f32 "
        "{%0,%1,%2,%3}, {%4,%5,%6,%7}, {%8,%9}, {%0,%1,%2,%3};"
        : "+f"(c[0]), "+f"(c[1]), "+f"(c[2]), "+f"(c[3])
        : "r"(a[0]), "r"(a[1]), "r"(a[2]), "r"(a[3]), "r"(b[0]), "r"(b[1]));
}
__device__ __forceinline__ void mma16816h(float* c, const uint32_t* a, const uint32_t* b) {
    asm volatile("mma.sync.aligned.m16n8k16.row.col.f32.f16.f16.f32 "
        "{%0,%1,%2,%3}, {%4,%5,%6,%7}, {%8,%9}, {%0,%1,%2,%3};"
        : "+f"(c[0]), "+f"(c[1]), "+f"(c[2]), "+f"(c[3])
        : "r"(a[0]), "r"(a[1]), "r"(a[2]), "r"(a[3]), "r"(b[0]), "r"(b[1]));
}
__device__ __forceinline__ uint32_t cvt2(float hi, float lo) {
    uint32_t r; asm("cvt.rn.bf16x2.f32 %0, %1, %2;" : "=r"(r) : "f"(hi), "f"(lo));
    return r;
}
__device__ __forceinline__ uint32_t cvth2(float hi, float lo) {
    uint32_t r; asm("cvt.rn.f16x2.f32 %0, %1, %2;" : "=r"(r) : "f"(hi), "f"(lo));
    return r;
}
__device__ __forceinline__ void split2(float a, float b, uint32_t& h, uint32_t& lo) {
    h = cvt2(b, a);
    float ha = __uint_as_float(h << 16);
    float hb = __uint_as_float(h & 0xffff0000u);
    lo = cvt2(b - hb, a - ha);
}

// ---------------- scratch ----------------
__device__ float g_pbuf[256 * PCOLS];
__device__ float g_q[B_ * H_ * N_ * DH_];
__device__ float g_k[B_ * HK_ * N_ * DH_];
__device__ float g_v[B_ * HK_ * N_ * DH_];
__device__ float g_pacc[128 * NSP2 * 64 * 128];
__device__ float g_pl[128 * NSP2 * 64];
__device__ __align__(16) __nv_bfloat16 g_wh[WB_ROWS * 4096];
__device__ __align__(16) __nv_bfloat16 g_wl[WB_ROWS * 4096];
__device__ __align__(16) __nv_bfloat16 g_xh[256 * 4096];
__device__ __align__(16) __nv_bfloat16 g_xl[256 * 4096];
__device__ __align__(16) __nv_bfloat16 g_zh[256 * 4096];
__device__ __align__(16) __nv_bfloat16 g_zl[256 * 4096];
__device__ __align__(16) __half       g_kf[128 * TPC * 128];
__device__ __align__(16) __half       g_vf[128 * TPC * 128];

// ---------------- weight transpose + bf16 split (n_base selects portion) ------
__global__ __launch_bounds__(256) void conv_w(
    const float* __restrict__ wq, const float* __restrict__ wk,
    const float* __restrict__ wv, const float* __restrict__ wo, int n_base)
{
    const int l = threadIdx.x & 31, w = threadIdx.x >> 5;
    const int k0 = (blockIdx.x << 6) + (w << 3);
    const int n0 = n_base + (blockIdx.y << 7) + (l << 2);

    const float* src; int nn, pitch;
    if (n0 < 4096)      { src = wq; nn = n0;        pitch = 4096; }
    else if (n0 < 5120) { src = wk; nn = n0 - 4096; pitch = 1024; }
    else if (n0 < 6144) { src = wv; nn = n0 - 5120; pitch = 1024; }
    else                { src = wo; nn = n0 - 6144; pitch = 4096; }

    float4 v[8];
#pragma unroll
    for (int j = 0; j < 8; j++)
        v[j] = *(const float4*)(src + (long long)(k0 + j) * pitch + nn);
    const float* vp = (const float*)v;

#pragma unroll
    for (int n = 0; n < 4; n++) {
        uint32_t hi[4], lo[4];
#pragma unroll
        for (int kp = 0; kp < 4; kp++)
            split2(vp[(2 * kp) * 4 + n], vp[(2 * kp + 1) * 4 + n], hi[kp], lo[kp]);
        long long o = (long long)(n0 + n) * 4096 + k0;
        *(uint4*)(g_wh + o) = make_uint4(hi[0], hi[1], hi[2], hi[3]);
        *(uint4*)(g_wl + o) = make_uint4(lo[0], lo[1], lo[2], lo[3]);
    }
}

// ---------------- activation bf16 split ----------------
__global__ __launch_bounds__(256) void conv_split(
    const float* __restrict__ src, __nv_bfloat16* __restrict__ hh,
    __nv_bfloat16* __restrict__ ll, int n4)
{
    int i = blockIdx.x * blockDim.x + threadIdx.x;
    if (i >= n4) return;
    float4 f = *(const float4*)(src + (i << 2));
    uint32_t h0, l0, h1, l1;
    split2(f.x, f.y, h0, l0);
    split2(f.z, f.w, h1, l1);
    *(uint2*)(hh + (i << 2)) = make_uint2(h0, h1);
    *(uint2*)(ll + (i << 2)) = make_uint2(l0, l1);
}

// ---------------- HMMA bf16x3 GEMM (unchanged) ----------------
#define HSM_STAGE 24576
#define HSM_B_OFF 16384
#define HSM_TOT   49152

__global__ __launch_bounds__(256) void hgemm(
    const __nv_bfloat16* __restrict__ Ah, const __nv_bfloat16* __restrict__ Al,
    int wb_off, float* __restrict__ C, int ldc)
{
    extern __shared__ char smr[];
    const int tid = threadIdx.x;
    const int l = tid & 31, w = tid >> 5;
    const int wm = w >> 1, wn = w & 1;
    const int bn = blockIdx.x << 6, bm = blockIdx.y << 7;
    const uint32_t smb = (uint32_t)__cvta_generic_to_shared(smr);

    const __nv_bfloat16* ah = Ah + (long long)bm * 4096;
    const __nv_bfloat16* al = Al + (long long)bm * 4096;
    const __nv_bfloat16* bh = g_wh + (long long)(wb_off + bn) * 4096;
    const __nv_bfloat16* bl = g_wl + (long long)(wb_off + bn) * 4096;

    float acc[2][4][4];
#pragma unroll
    for (int i = 0; i < 2; i++)
#pragma unroll
        for (int j = 0; j < 4; j++)
#pragma unroll
            for (int q = 0; q < 4; q++) acc[i][j][q] = 0.f;

    auto load_stage = [&](uint32_t sbase, int k0) {
#pragma unroll
        for (int i = 0; i < 6; i++) {
            int s = tid + (i << 8);
            const __nv_bfloat16 *hsrc, *lsrc;
            uint32_t dst; int idx;
            if (s < 1024) { hsrc = ah; lsrc = al; dst = sbase;             idx = s; }
            else          { hsrc = bh; lsrc = bl; dst = sbase + HSM_B_OFF; idx = s - 1024; }
            int row = idx >> 3, g = idx & 7;
            const __nv_bfloat16* src = (g < 4 ? hsrc : lsrc)
                                     + (long long)row * 4096 + k0 + ((g & 3) << 3);
            cpa16(dst + row * 128 + ((g ^ (row & 7)) << 4), src, 16);
        }
        cpa_commit();
    };

    load_stage(smb, 0);

    const int a_row = (l & 15);
    const int a_half = l >> 4;
    const int b_rl = (l & 7) + ((l >> 4) << 3);
    const int b_half = (l >> 3) & 1;

    for (int c = 0; c < 128; c++) {
        cpa_wait0();
        __syncthreads();
        const uint32_t st = smb + (c & 1) * HSM_STAGE;
        if (c + 1 < 128) load_stage(smb + ((c + 1) & 1) * HSM_STAGE, (c + 1) << 5);

#pragma unroll
        for (int ks = 0; ks < 2; ks++) {
            uint32_t ahf[2][4], alf[2][4], bhf[2][4], blf[2][4];
#pragma unroll
            for (int mt = 0; mt < 2; mt++) {
                int row = (wm << 5) + (mt << 4) + a_row;
                int gh = (ks << 1) + a_half;
                uint32_t base = st + row * 128;
                ldsm4(ahf[mt], base + ((gh ^ (row & 7)) << 4));
                int gl = gh + 4;
                ldsm4(alf[mt], base + ((gl ^ (row & 7)) << 4));
            }
#pragma unroll
            for (int np = 0; np < 2; np++) {
                int row = (wn << 5) + (np << 4) + b_rl;
                int gh = (ks << 1) + b_half;
                uint32_t base = st + HSM_B_OFF + row * 128;
                ldsm4(bhf[np], base + ((gh ^ (row & 7)) << 4));
                int gl = gh + 4;
                ldsm4(blf[np], base + ((gl ^ (row & 7)) << 4));
            }
#pragma unroll
            for (int mt = 0; mt < 2; mt++)
#pragma unroll
                for (int np = 0; np < 2; np++)
#pragma unroll
                    for (int hh = 0; hh < 2; hh++) {
                        float* at = acc[mt][(np << 1) + hh];
                        mma16816(at, ahf[mt], &bhf[np][hh << 1]);
                        mma16816(at, ahf[mt], &blf[np][hh << 1]);
                        mma16816(at, alf[mt], &bhf[np][hh << 1]);
                    }
        }
        __syncthreads();
    }

#pragma unroll
    for (int mt = 0; mt < 2; mt++) {
#pragma unroll
        for (int nt = 0; nt < 4; nt++) {
            long long r0 = bm + (wm << 5) + (mt << 4) + (l >> 2);
            int col = bn + (wn << 5) + (nt << 3) + ((l & 3) << 1);
            float* cp = C + r0 * ldc + col;
            *(float2*)cp             = make_float2(acc[mt][nt][0], acc[mt][nt][1]);
            *(float2*)(cp + 8 * ldc) = make_float2(acc[mt][nt][2], acc[mt][nt][3]);
        }
    }
}

// ---------------- RoPE + rearrange ----------------
__global__ __launch_bounds__(256) void rope_qk(
    const float* __restrict__ pbuf, const float* __restrict__ fc, const float* __restrict__ fs)
{
    int i = blockIdx.x * blockDim.x + threadIdx.x;
    const int TOT = B_ * N_ * (H_ + HK_) * 64;
    if (i >= TOT) return;
    int pr   = i & 63;
    int head = (i >> 6) % (H_ + HK_);
    int bn   = (i >> 6) / (H_ + HK_);
    int n    = bn % N_;
    int b    = bn / N_;
    float c = fc[n * 64 + pr];
    float s = fs[n * 64 + pr];
    const float* row = pbuf + (long long)(b * N_ + n) * PCOLS;
    if (head < H_) {
        float a  = row[head * DH_ + 2 * pr];
        float bb = row[head * DH_ + 2 * pr + 1];
        float* q = g_q + ((long long)(b * H_ + head) * N_ + n) * DH_ + 2 * pr;
        q[0] = (a * c - bb * s) * SCALE;
        q[1] = (a * s + bb * c) * SCALE;
    } else {
        int hk = head - H_;
        float a  = row[H_ * DH_ + hk * DH_ + 2 * pr];
        float bb = row[H_ * DH_ + hk * DH_ + 2 * pr + 1];
        float* k = g_k + ((long long)(b * HK_ + hk) * N_ + n) * DH_ + 2 * pr;
        k[0] = a * c - bb * s;
        k[1] = a * s + bb * c;
    }
}

__global__ __launch_bounds__(256) void copy_v(const float* __restrict__ pbuf)
{
    int i = blockIdx.x * blockDim.x + threadIdx.x;
    if (i >= B_ * HK_ * N_ * DH_) return;
    int d  = i & 127;
    int n  = (i >> 7) & 15;
    int hk = (i >> 11) & 7;
    int b  = i >> 14;
    g_v[i] = pbuf[(long long)(b * N_ + n) * PCOLS + (H_ + HK_) * DH_ + hk * DH_ + d];
}

// ---------------- K+V cache -> fp16 [bhk][t][d]; processes t in [tbase, tbase+tcount) --
__global__ __launch_bounds__(256) void conv_kv(
    const float* __restrict__ cache_k, const float* __restrict__ cache_v,
    const int* __restrict__ sp, int ctx, int Tpad, int tbase, int tcount)
{
    int i = blockIdx.x * blockDim.x + threadIdx.x;
    if (i >= 128 * tcount * 16) return;
    int g8  = i & 15;
    int t   = tbase + (i >> 4) % tcount;
    int bhk = i / (tcount << 4);
    const int start = sp[0], tend = start + N_;
    const int sel = blockIdx.y;
    const float* cache = sel ? cache_v : cache_k;
    const float* fresh = sel ? g_v : g_k;
    __half* dst = sel ? g_vf : g_kf;

    float4 v0, v1;
    if (t < start) {
        const float* p = cache + ((long long)bhk * ctx + t) * DH_ + (g8 << 3);
        v0 = *(const float4*)p; v1 = *(const float4*)(p + 4);
    } else if (t < tend) {
        const float* p = fresh + ((long long)bhk * N_ + (t - start)) * DH_ + (g8 << 3);
        v0 = *(const float4*)p; v1 = *(const float4*)(p + 4);
    } else {
        v0 = make_float4(0.f, 0.f, 0.f, 0.f); v1 = v0;
    }
    long long o = ((long long)bhk * Tpad + t) * 128 + (g8 << 3);
    *(uint4*)(dst + o) = make_uint4(cvth2(v0.y, v0.x), cvth2(v0.w, v0.z),
                                    cvth2(v1.y, v1.x), cvth2(v1.w, v1.z));
}

// ---------------- attn (unchanged from R15) ----------------
#define ASM_Q   0
#define ASM_ST  16384
#define ASM_STRIDE 32768
#define ASM_TOT (16384 + 3 * 32768)

__global__ __launch_bounds__(256, 1) void attn(const int* __restrict__ sp, int Tpad)
{
    extern __shared__ char smr[];
    const int tid = threadIdx.x;
    const int l = tid & 31, w = tid >> 5;
    const int wm = w >> 1, wn = w & 1;
    const int bhk = blockIdx.x;
    const int ks  = blockIdx.y;
    const int start = sp[0];
    const int tend  = start + N_;
    const uint32_t smb = (uint32_t)__cvta_generic_to_shared(smr);

    const float* qbase = g_q + ((long long)(bhk >> 3) * H_ + (bhk & 7) * REP_) * N_ * DH_;
#pragma unroll
    for (int i = 0; i < 4; i++) {
        int j = tid + (i << 8);
        int row = j >> 4, g = j & 15;
        const float* src = qbase + row * 128 + (g << 3);
        float4 f0 = *(const float4*)src;
        float4 f1 = *(const float4*)(src + 4);
        uint32_t off = row * 256 + ((g ^ (row & 7)) << 4);
        *(uint4*)(smr + ASM_Q + off) = make_uint4(
            cvth2(f0.y, f0.x), cvth2(f0.w, f0.z), cvth2(f1.y, f1.x), cvth2(f1.w, f1.z));
    }

    auto load_stage = [&](uint32_t sbase, int t0) {
#pragma unroll
        for (int i = 0; i < 8; i++) {
            int s = tid + (i << 8);
            int sel = s >> 10, idx = s & 1023;
            int row = idx >> 4, g = idx & 15;
            const __half* src = (sel ? g_vf : g_kf)
                + ((long long)bhk * Tpad + t0 + row) * 128 + (g << 3);
            cpa16(sbase + sel * 16384 + row * 256 + ((g ^ (row & 7)) << 4), src, 16);
        }
        cpa_commit();
    };

    const int nc = (tend - ks * 64 + 511) >> 9;
    load_stage(smb + ASM_ST, ks * 64);
    if (nc > 1) load_stage(smb + ASM_ST + ASM_STRIDE, ks * 64 + 512);

    float oacc[16][4];
#pragma unroll
    for (int i = 0; i < 16; i++)
#pragma unroll
        for (int q = 0; q < 4; q++) oacc[i][q] = 0.f;
    float lsumA = 0.f, lsumB = 0.f;
    const int limA = start + (l >> 2);
    const int limB = limA + 8;

    const int a_row = l & 15, a_half = l >> 4;
    const int b_rl = (l & 7) + ((l >> 4) << 3);
    const int b_half = (l >> 3) & 1;
    const int tg = l & 3;
    const int v_tl = (l & 7) + (((l >> 3) & 1) << 3);
    const int v_gh = l >> 4;

    for (int ci = 0; ci < nc; ci++) {
        const int t0 = ks * 64 + (ci << 9);
        if (ci + 2 <= nc) cpa_wait1(); else cpa_wait0();
        __syncthreads();
        const uint32_t st = smb + ASM_ST + (ci % 3) * ASM_STRIDE;
        if (ci + 2 < nc)
            load_stage(smb + ASM_ST + ((ci + 2) % 3) * ASM_STRIDE, t0 + 1024);

        float sacc[4][4];
#pragma unroll
        for (int i = 0; i < 4; i++)
#pragma unroll
            for (int q = 0; q < 4; q++) sacc[i][q] = 0.f;
#pragma unroll
        for (int kk = 0; kk < 8; kk++) {
            uint32_t ah[4], bh[2][4];
            {
                int row = (wm << 4) + a_row;
                int g = (kk << 1) + a_half;
                ldsm4(ah, smb + ASM_Q + row * 256 + ((g ^ (row & 7)) << 4));
            }
#pragma unroll
            for (int np = 0; np < 2; np++) {
                int row = (wn << 5) + (np << 4) + b_rl;
                int g = (kk << 1) + b_half;
                ldsm4(bh[np], st + row * 256 + ((g ^ (row & 7)) << 4));
            }
#pragma unroll
            for (int np = 0; np < 2; np++)
#pragma unroll
                for (int hh = 0; hh < 2; hh++)
                    mma16816h(sacc[(np << 1) + hh], ah, &bh[np][hh << 1]);
        }

        uint32_t pa[2][4];
#pragma unroll
        for (int nt = 0; nt < 4; nt++) {
            int tb = t0 + (wn << 5) + (nt << 3) + (tg << 1);
            float p0 = (tb     <= limA) ? __expf(sacc[nt][0]) : 0.f;
            float p1 = (tb + 1 <= limA) ? __expf(sacc[nt][1]) : 0.f;
            float p2 = (tb     <= limB) ? __expf(sacc[nt][2]) : 0.f;
            float p3 = (tb + 1 <= limB) ? __expf(sacc[nt][3]) : 0.f;
            lsumA += p0 + p1;
            lsumB += p2 + p3;
            int kt = nt >> 1, hf = nt & 1;
            pa[kt][(hf << 1) + 0] = cvth2(p1, p0);
            pa[kt][(hf << 1) + 1] = cvth2(p3, p2);
        }

        const uint32_t stV = st + 16384;
#pragma unroll
        for (int kt = 0; kt < 2; kt++) {
            int trow = (wn << 5) + (kt << 4) + v_tl;
            uint32_t rbase = stV + trow * 256;
            int rsw = trow & 7;
#pragma unroll
            for (int np = 0; np < 8; np++) {
                int g = (np << 1) + v_gh;
                uint32_t bv[4];
                ldsm4t(bv, rbase + ((g ^ rsw) << 4));
                mma16816h(oacc[(np << 1) + 0], pa[kt], &bv[0]);
                mma16816h(oacc[(np << 1) + 1], pa[kt], &bv[2]);
            }
        }
    }

#pragma unroll
    for (int m = 1; m < 4; m <<= 1) {
        lsumA += __shfl_xor_sync(0xffffffffu, lsumA, m);
        lsumB += __shfl_xor_sync(0xffffffffu, lsumB, m);
    }

    const int spn = (ks << 1) + wn;
    const long long pb = ((long long)bhk * NSP2 + spn) * 64;
    if (tg == 0) {
        g_pl[pb + (wm << 4) + (l >> 2)]     = lsumA;
        g_pl[pb + (wm << 4) + (l >> 2) + 8] = lsumB;
    }
#pragma unroll
    for (int nt = 0; nt < 16; nt++) {
        long long r0 = pb + (wm << 4) + (l >> 2);
        int d = (nt << 3) + (tg << 1);
        *(float2*)(g_pacc + r0 * 128 + d)       = make_float2(oacc[nt][0], oacc[nt][1]);
        *(float2*)(g_pacc + (r0 + 8) * 128 + d) = make_float2(oacc[nt][2], oacc[nt][3]);
    }
}

// ---------------- combine partials -> zh/zl ----------------
__global__ __launch_bounds__(256) void attn_combine(
    __nv_bfloat16* __restrict__ zh, __nv_bfloat16* __restrict__ zl)
{
    int idx = blockIdx.x * blockDim.x + threadIdx.x;
    if (idx >= 128 * 64 * 32) return;
    int dq   = idx & 31;
    int row  = (idx >> 5) & 63;
    int bhk  = idx >> 11;
    int d0   = dq << 2;
    float4 a = make_float4(0.f, 0.f, 0.f, 0.f);
    float lv = 0.f;
#pragma unroll
    for (int spn = 0; spn < NSP2; spn++) {
        long long base = ((long long)bhk * NSP2 + spn) * 64 + row;
        float4 t = *(const float4*)(g_pacc + base * 128 + d0);
        a.x += t.x; a.y += t.y; a.z += t.z; a.w += t.w;
        lv += g_pl[base];
    }
    float inv = __frcp_rn(lv);
    float v0 = a.x * inv, v1 = a.y * inv, v2 = a.z * inv, v3 = a.w * inv;
    uint32_t h0, l0, h1, l1;
    split2(v0, v1, h0, l0);
    split2(v2, v3, h1, l1);
    int r = row >> 4, n = row & 15;
    int b = bhk >> 3, hk = bhk & 7;
    long long o = (long long)(b * N_ + n) * D_ + (hk * REP_ + r) * DH_ + d0;
    *(uint2*)(zh + o) = make_uint2(h0, h1);
    *(uint2*)(zl + o) = make_uint2(l0, l1);
}

// ---------------- launch (fork/join streams for overlap) ----------------
extern "C" void kernel_launch(void* const* d_in, const int* in_sizes, int n_in,
                              void* d_out, int out_size)
{
    const float* x  = (const float*)d_in[0];
    const float* fc = (const float*)d_in[1];
    const float* fs = (const float*)d_in[2];
    const float* ck = (const float*)d_in[4];
    const float* cv = (const float*)d_in[5];
    const float* wq = (const float*)d_in[6];
    const float* wk = (const float*)d_in[7];
    const float* wv = (const float*)d_in[8];
    const float* wo = (const float*)d_in[9];
    const int*   sp = (const int*)d_in[10];
    float* out = (float*)d_out;

    int ctx  = in_sizes[4] / (B_ * HK_ * DH_);
    int T    = in_sizes[3] / N_;
    int Tpad = ((T + 63) / 64) * 64;
    if (Tpad > TPC) Tpad = TPC;
    int start_h = T - N_;                     // host-side start (sp still read on device)

    float* pbuf; cudaGetSymbolAddress((void**)&pbuf, g_pbuf);
    __nv_bfloat16 *xh, *xl, *zh, *zl;
    cudaGetSymbolAddress((void**)&xh, g_xh);
    cudaGetSymbolAddress((void**)&xl, g_xl);
    cudaGetSymbolAddress((void**)&zh, g_zh);
    cudaGetSymbolAddress((void**)&zl, g_zl);

    // side stream + events, created once on first (non-captured) call
    static cudaStream_t s2 = []{ cudaStream_t s;
        cudaStreamCreateWithFlags(&s, cudaStreamNonBlocking); return s; }();
    static cudaEvent_t evF = []{ cudaEvent_t e;
        cudaEventCreateWithFlags(&e, cudaEventDisableTiming); return e; }();
    static cudaEvent_t evJ = []{ cudaEvent_t e;
        cudaEventCreateWithFlags(&e, cudaEventDisableTiming); return e; }();

    dim3 blk(256);

    // fork
    cudaEventRecord(evF, 0);
    cudaStreamWaitEvent(s2, evF, 0);

    // side stream: wo weight conversion + cache-portion K/V conversion (independent)
    conv_w<<<dim3(64, 32), blk, 0, s2>>>(wq, wk, wv, wo, 6144);
    conv_kv<<<dim3((128 * start_h * 16 + 255) / 256, 2), blk, 0, s2>>>(
        ck, cv, sp, ctx, Tpad, 0, start_h);
    cudaEventRecord(evJ, s2);

    // main stream: QKV path
    conv_w<<<dim3(64, 48), blk>>>(wq, wk, wv, wo, 0);
    conv_split<<<(256 * 1024 + 255) / 256, blk>>>(x, xh, xl, 256 * 1024);

    cudaFuncSetAttribute(hgemm, cudaFuncAttributeMaxDynamicSharedMemorySize, HSM_TOT);
    hgemm<<<dim3(96, 2), blk, HSM_TOT>>>(xh, xl, 0, pbuf, PCOLS);

    rope_qk<<<(B_ * N_ * (H_ + HK_) * 64 + 255) / 256, blk>>>(pbuf, fc, fs);
    copy_v<<<(B_ * HK_ * N_ * DH_ + 255) / 256, blk>>>(pbuf);

    // fresh + pad portion of K/V conversion (needs rope/copy_v)
    conv_kv<<<dim3((128 * (Tpad - start_h) * 16 + 255) / 256, 2), blk>>>(
        ck, cv, sp, ctx, Tpad, start_h, Tpad - start_h);

    // join: attn needs cache conversion; final hgemm needs wo weights
    cudaStreamWaitEvent(0, evJ, 0);

    cudaFuncSetAttribute(attn, cudaFuncAttributeMaxDynamicSharedMemorySize, ASM_TOT);
    attn<<<dim3(128, 8), blk, ASM_TOT>>>(sp, Tpad);
    attn_combine<<<(128 * 64 * 32 + 255) / 256, blk>>>(zh, zl);

    hgemm<<<dim3(64, 2), blk, HSM_TOT>>>(zh, zl, 6144, out, D_);
}

// round 17
// speedup vs baseline: 1.9245x; 1.7097x over previous
#include <cuda_runtime.h>
#include <cuda_bf16.h>
#include <cuda_fp16.h>
#include <cstdint>

#define B_    16
#define N_    16
#define D_    4096
#define H_    32
#define HK_   8
#define REP_  4
#define DH_   128
#define PCOLS 6144
#define SCALE 0.08838834764831844f
#define WB_ROWS 10240
#define TPC   2112
#define NSP2  16

typedef unsigned long long u64;

__device__ __forceinline__ void cpa16(uint32_t dst, const void* src, int sz) {
    asm volatile("cp.async.cg.shared.global [%0], [%1], 16, %2;"
                 :: "r"(dst), "l"(src), "r"(sz));
}
__device__ __forceinline__ void cpa_commit() {
    asm volatile("cp.async.commit_group;" ::: "memory");
}
__device__ __forceinline__ void cpa_wait0() {
    asm volatile("cp.async.wait_group 0;" ::: "memory");
}
__device__ __forceinline__ void cpa_wait1() {
    asm volatile("cp.async.wait_group 1;" ::: "memory");
}
__device__ __forceinline__ void ldsm4(uint32_t* r, uint32_t addr) {
    asm volatile("ldmatrix.sync.aligned.m8n8.x4.shared.b16 {%0,%1,%2,%3}, [%4];"
                 : "=r"(r[0]), "=r"(r[1]), "=r"(r[2]), "=r"(r[3]) : "r"(addr));
}
__device__ __forceinline__ void ldsm4t(uint32_t* r, uint32_t addr) {
    asm volatile("ldmatrix.sync.aligned.m8n8.x4.trans.shared.b16 {%0,%1,%2,%3}, [%4];"
                 : "=r"(r[0]), "=r"(r[1]), "=r"(r[2]), "=r"(r[3]) : "r"(addr));
}
__device__ __forceinline__ void mma16816h(float* c, const uint32_t* a, const uint32_t* b) {
    asm volatile("mma.sync.aligned.m16n8k16.row.col.f32.f16.f16.f32 "
        "{%0,%1,%2,%3}, {%4,%5,%6,%7}, {%8,%9}, {%0,%1,%2,%3};"
        : "+f"(c[0]), "+f"(c[1]), "+f"(c[2]), "+f"(c[3])
        : "r"(a[0]), "r"(a[1]), "r"(a[2]), "r"(a[3]), "r"(b[0]), "r"(b[1]));
}
__device__ __forceinline__ uint32_t cvth2(float hi, float lo) {
    uint32_t r; asm("cvt.rn.f16x2.f32 %0, %1, %2;" : "=r"(r) : "f"(hi), "f"(lo));
    return r;
}

// ---------------- scratch ----------------
__device__ float g_pbuf[256 * PCOLS];
__device__ float g_q[B_ * H_ * N_ * DH_];
__device__ float g_k[B_ * HK_ * N_ * DH_];
__device__ float g_v[B_ * HK_ * N_ * DH_];
__device__ float g_pacc[128 * NSP2 * 64 * 128];
__device__ float g_pl[128 * NSP2 * 64];
__device__ __align__(16) __half g_wf[WB_ROWS * 4096];   // fp16 weights [n][k]
__device__ __align__(16) __half g_xf[256 * 4096];       // fp16 x
__device__ __align__(16) __half g_zf[256 * 4096];       // fp16 z
__device__ __align__(16) __half g_kf[128 * TPC * 128];
__device__ __align__(16) __half g_vf[128 * TPC * 128];

// ---------------- weight transpose + fp16 convert (register gather) -----------
__global__ __launch_bounds__(256) void conv_w(
    const float* __restrict__ wq, const float* __restrict__ wk,
    const float* __restrict__ wv, const float* __restrict__ wo, int n_base)
{
    const int l = threadIdx.x & 31, w = threadIdx.x >> 5;
    const int k0 = (blockIdx.x << 6) + (w << 3);
    const int n0 = n_base + (blockIdx.y << 7) + (l << 2);

    const float* src; int nn, pitch;
    if (n0 < 4096)      { src = wq; nn = n0;        pitch = 4096; }
    else if (n0 < 5120) { src = wk; nn = n0 - 4096; pitch = 1024; }
    else if (n0 < 6144) { src = wv; nn = n0 - 5120; pitch = 1024; }
    else                { src = wo; nn = n0 - 6144; pitch = 4096; }

    float4 v[8];
#pragma unroll
    for (int j = 0; j < 8; j++)
        v[j] = *(const float4*)(src + (long long)(k0 + j) * pitch + nn);
    const float* vp = (const float*)v;

#pragma unroll
    for (int n = 0; n < 4; n++) {
        uint32_t h[4];
#pragma unroll
        for (int kp = 0; kp < 4; kp++)
            h[kp] = cvth2(vp[(2 * kp + 1) * 4 + n], vp[(2 * kp) * 4 + n]);
        *(uint4*)(g_wf + (long long)(n0 + n) * 4096 + k0) =
            make_uint4(h[0], h[1], h[2], h[3]);
    }
}

// ---------------- fp32 -> fp16 convert (vectorized) ----------------
__global__ __launch_bounds__(256) void conv_half(
    const float* __restrict__ src, __half* __restrict__ dst, int n4)
{
    int i = blockIdx.x * blockDim.x + threadIdx.x;
    if (i >= n4) return;
    float4 f = *(const float4*)(src + (i << 2));
    *(uint2*)(dst + (i << 2)) = make_uint2(cvth2(f.y, f.x), cvth2(f.w, f.z));
}

// ---------------- HMMA fp16 GEMM: 128x64 tiles, K-chunks of 64 ----------------
#define HSM_STAGE 24576      /* A 16K + B 8K */
#define HSM_B_OFF 16384
#define HSM_TOT   49152

__global__ __launch_bounds__(256) void hgemm(
    const __half* __restrict__ A, int wb_off, float* __restrict__ C, int ldc)
{
    extern __shared__ char smr[];
    const int tid = threadIdx.x;
    const int l = tid & 31, w = tid >> 5;
    const int wm = w >> 1, wn = w & 1;
    const int bn = blockIdx.x << 6, bm = blockIdx.y << 7;
    const uint32_t smb = (uint32_t)__cvta_generic_to_shared(smr);

    const __half* a = A + (long long)bm * 4096;
    const __half* b = g_wf + (long long)(wb_off + bn) * 4096;

    float acc[2][4][4];
#pragma unroll
    for (int i = 0; i < 2; i++)
#pragma unroll
        for (int j = 0; j < 4; j++)
#pragma unroll
            for (int q = 0; q < 4; q++) acc[i][j][q] = 0.f;

    // stage: A 128 rows x 128B (64 fp16 k) + B 64 rows x 128B; 1536 granule tasks
    auto load_stage = [&](uint32_t sbase, int k0) {
#pragma unroll
        for (int i = 0; i < 6; i++) {
            int s = tid + (i << 8);
            const __half* src; uint32_t dst; int idx;
            if (s < 1024) { src = a; dst = sbase;             idx = s; }
            else          { src = b; dst = sbase + HSM_B_OFF; idx = s - 1024; }
            int row = idx >> 3, g = idx & 7;
            cpa16(dst + row * 128 + ((g ^ (row & 7)) << 4),
                  src + (long long)row * 4096 + k0 + (g << 3), 16);
        }
        cpa_commit();
    };

    load_stage(smb, 0);

    const int a_row = l & 15;
    const int a_half = l >> 4;
    const int b_rl = (l & 7) + ((l >> 4) << 3);
    const int b_half = (l >> 3) & 1;

    for (int c = 0; c < 64; c++) {
        cpa_wait0();
        __syncthreads();
        const uint32_t st = smb + (c & 1) * HSM_STAGE;
        if (c + 1 < 64) load_stage(smb + ((c + 1) & 1) * HSM_STAGE, (c + 1) << 6);

#pragma unroll
        for (int ks = 0; ks < 4; ks++) {
            uint32_t ahf[2][4], bhf[2][4];
#pragma unroll
            for (int mt = 0; mt < 2; mt++) {
                int row = (wm << 5) + (mt << 4) + a_row;
                int g = (ks << 1) + a_half;
                ldsm4(ahf[mt], st + row * 128 + ((g ^ (row & 7)) << 4));
            }
#pragma unroll
            for (int np = 0; np < 2; np++) {
                int row = (wn << 5) + (np << 4) + b_rl;
                int g = (ks << 1) + b_half;
                ldsm4(bhf[np], st + HSM_B_OFF + row * 128 + ((g ^ (row & 7)) << 4));
            }
#pragma unroll
            for (int mt = 0; mt < 2; mt++)
#pragma unroll
                for (int np = 0; np < 2; np++)
#pragma unroll
                    for (int hh = 0; hh < 2; hh++)
                        mma16816h(acc[mt][(np << 1) + hh], ahf[mt], &bhf[np][hh << 1]);
        }
        __syncthreads();
    }

#pragma unroll
    for (int mt = 0; mt < 2; mt++) {
#pragma unroll
        for (int nt = 0; nt < 4; nt++) {
            long long r0 = bm + (wm << 5) + (mt << 4) + (l >> 2);
            int col = bn + (wn << 5) + (nt << 3) + ((l & 3) << 1);
            float* cp = C + r0 * ldc + col;
            *(float2*)cp             = make_float2(acc[mt][nt][0], acc[mt][nt][1]);
            *(float2*)(cp + 8 * ldc) = make_float2(acc[mt][nt][2], acc[mt][nt][3]);
        }
    }
}

// ---------------- RoPE + rearrange ----------------
__global__ __launch_bounds__(256) void rope_qk(
    const float* __restrict__ pbuf, const float* __restrict__ fc, const float* __restrict__ fs)
{
    int i = blockIdx.x * blockDim.x + threadIdx.x;
    const int TOT = B_ * N_ * (H_ + HK_) * 64;
    if (i >= TOT) return;
    int pr   = i & 63;
    int head = (i >> 6) % (H_ + HK_);
    int bn   = (i >> 6) / (H_ + HK_);
    int n    = bn % N_;
    int b    = bn / N_;
    float c = fc[n * 64 + pr];
    float s = fs[n * 64 + pr];
    const float* row = pbuf + (long long)(b * N_ + n) * PCOLS;
    if (head < H_) {
        float a  = row[head * DH_ + 2 * pr];
        float bb = row[head * DH_ + 2 * pr + 1];
        float* q = g_q + ((long long)(b * H_ + head) * N_ + n) * DH_ + 2 * pr;
        q[0] = (a * c - bb * s) * SCALE;
        q[1] = (a * s + bb * c) * SCALE;
    } else {
        int hk = head - H_;
        float a  = row[H_ * DH_ + hk * DH_ + 2 * pr];
        float bb = row[H_ * DH_ + hk * DH_ + 2 * pr + 1];
        float* k = g_k + ((long long)(b * HK_ + hk) * N_ + n) * DH_ + 2 * pr;
        k[0] = a * c - bb * s;
        k[1] = a * s + bb * c;
    }
}

__global__ __launch_bounds__(256) void copy_v(const float* __restrict__ pbuf)
{
    int i = blockIdx.x * blockDim.x + threadIdx.x;
    if (i >= B_ * HK_ * N_ * DH_) return;
    int d  = i & 127;
    int n  = (i >> 7) & 15;
    int hk = (i >> 11) & 7;
    int b  = i >> 14;
    g_v[i] = pbuf[(long long)(b * N_ + n) * PCOLS + (H_ + HK_) * DH_ + hk * DH_ + d];
}

// ---------------- K+V cache -> fp16 [bhk][t][d]; t in [tbase, tbase+tcount) ----
__global__ __launch_bounds__(256) void conv_kv(
    const float* __restrict__ cache_k, const float* __restrict__ cache_v,
    const int* __restrict__ sp, int ctx, int Tpad, int tbase, int tcount)
{
    int i = blockIdx.x * blockDim.x + threadIdx.x;
    if (i >= 128 * tcount * 16) return;
    int g8  = i & 15;
    int t   = tbase + (i >> 4) % tcount;
    int bhk = i / (tcount << 4);
    const int start = sp[0], tend = start + N_;
    const int sel = blockIdx.y;
    const float* cache = sel ? cache_v : cache_k;
    const float* fresh = sel ? g_v : g_k;
    __half* dst = sel ? g_vf : g_kf;

    float4 v0, v1;
    if (t < start) {
        const float* p = cache + ((long long)bhk * ctx + t) * DH_ + (g8 << 3);
        v0 = *(const float4*)p; v1 = *(const float4*)(p + 4);
    } else if (t < tend) {
        const float* p = fresh + ((long long)bhk * N_ + (t - start)) * DH_ + (g8 << 3);
        v0 = *(const float4*)p; v1 = *(const float4*)(p + 4);
    } else {
        v0 = make_float4(0.f, 0.f, 0.f, 0.f); v1 = v0;
    }
    long long o = ((long long)bhk * Tpad + t) * 128 + (g8 << 3);
    *(uint4*)(dst + o) = make_uint4(cvth2(v0.y, v0.x), cvth2(v0.w, v0.z),
                                    cvth2(v1.y, v1.x), cvth2(v1.w, v1.z));
}

// ---------------- attn (unchanged from R15/R16) ----------------
#define ASM_Q   0
#define ASM_ST  16384
#define ASM_STRIDE 32768
#define ASM_TOT (16384 + 3 * 32768)

__global__ __launch_bounds__(256, 1) void attn(const int* __restrict__ sp, int Tpad)
{
    extern __shared__ char smr[];
    const int tid = threadIdx.x;
    const int l = tid & 31, w = tid >> 5;
    const int wm = w >> 1, wn = w & 1;
    const int bhk = blockIdx.x;
    const int ks  = blockIdx.y;
    const int start = sp[0];
    const int tend  = start + N_;
    const uint32_t smb = (uint32_t)__cvta_generic_to_shared(smr);

    const float* qbase = g_q + ((long long)(bhk >> 3) * H_ + (bhk & 7) * REP_) * N_ * DH_;
#pragma unroll
    for (int i = 0; i < 4; i++) {
        int j = tid + (i << 8);
        int row = j >> 4, g = j & 15;
        const float* src = qbase + row * 128 + (g << 3);
        float4 f0 = *(const float4*)src;
        float4 f1 = *(const float4*)(src + 4);
        uint32_t off = row * 256 + ((g ^ (row & 7)) << 4);
        *(uint4*)(smr + ASM_Q + off) = make_uint4(
            cvth2(f0.y, f0.x), cvth2(f0.w, f0.z), cvth2(f1.y, f1.x), cvth2(f1.w, f1.z));
    }

    auto load_stage = [&](uint32_t sbase, int t0) {
#pragma unroll
        for (int i = 0; i < 8; i++) {
            int s = tid + (i << 8);
            int sel = s >> 10, idx = s & 1023;
            int row = idx >> 4, g = idx & 15;
            const __half* src = (sel ? g_vf : g_kf)
                + ((long long)bhk * Tpad + t0 + row) * 128 + (g << 3);
            cpa16(sbase + sel * 16384 + row * 256 + ((g ^ (row & 7)) << 4), src, 16);
        }
        cpa_commit();
    };

    const int nc = (tend - ks * 64 + 511) >> 9;
    load_stage(smb + ASM_ST, ks * 64);
    if (nc > 1) load_stage(smb + ASM_ST + ASM_STRIDE, ks * 64 + 512);

    float oacc[16][4];
#pragma unroll
    for (int i = 0; i < 16; i++)
#pragma unroll
        for (int q = 0; q < 4; q++) oacc[i][q] = 0.f;
    float lsumA = 0.f, lsumB = 0.f;
    const int limA = start + (l >> 2);
    const int limB = limA + 8;

    const int a_row = l & 15, a_half = l >> 4;
    const int b_rl = (l & 7) + ((l >> 4) << 3);
    const int b_half = (l >> 3) & 1;
    const int tg = l & 3;
    const int v_tl = (l & 7) + (((l >> 3) & 1) << 3);
    const int v_gh = l >> 4;

    for (int ci = 0; ci < nc; ci++) {
        const int t0 = ks * 64 + (ci << 9);
        if (ci + 2 <= nc) cpa_wait1(); else cpa_wait0();
        __syncthreads();
        const uint32_t st = smb + ASM_ST + (ci % 3) * ASM_STRIDE;
        if (ci + 2 < nc)
            load_stage(smb + ASM_ST + ((ci + 2) % 3) * ASM_STRIDE, t0 + 1024);

        float sacc[4][4];
#pragma unroll
        for (int i = 0; i < 4; i++)
#pragma unroll
            for (int q = 0; q < 4; q++) sacc[i][q] = 0.f;
#pragma unroll
        for (int kk = 0; kk < 8; kk++) {
            uint32_t ah[4], bh[2][4];
            {
                int row = (wm << 4) + a_row;
                int g = (kk << 1) + a_half;
                ldsm4(ah, smb + ASM_Q + row * 256 + ((g ^ (row & 7)) << 4));
            }
#pragma unroll
            for (int np = 0; np < 2; np++) {
                int row = (wn << 5) + (np << 4) + b_rl;
                int g = (kk << 1) + b_half;
                ldsm4(bh[np], st + row * 256 + ((g ^ (row & 7)) << 4));
            }
#pragma unroll
            for (int np = 0; np < 2; np++)
#pragma unroll
                for (int hh = 0; hh < 2; hh++)
                    mma16816h(sacc[(np << 1) + hh], ah, &bh[np][hh << 1]);
        }

        uint32_t pa[2][4];
#pragma unroll
        for (int nt = 0; nt < 4; nt++) {
            int tb = t0 + (wn << 5) + (nt << 3) + (tg << 1);
            float p0 = (tb     <= limA) ? __expf(sacc[nt][0]) : 0.f;
            float p1 = (tb + 1 <= limA) ? __expf(sacc[nt][1]) : 0.f;
            float p2 = (tb     <= limB) ? __expf(sacc[nt][2]) : 0.f;
            float p3 = (tb + 1 <= limB) ? __expf(sacc[nt][3]) : 0.f;
            lsumA += p0 + p1;
            lsumB += p2 + p3;
            int kt = nt >> 1, hf = nt & 1;
            pa[kt][(hf << 1) + 0] = cvth2(p1, p0);
            pa[kt][(hf << 1) + 1] = cvth2(p3, p2);
        }

        const uint32_t stV = st + 16384;
#pragma unroll
        for (int kt = 0; kt < 2; kt++) {
            int trow = (wn << 5) + (kt << 4) + v_tl;
            uint32_t rbase = stV + trow * 256;
            int rsw = trow & 7;
#pragma unroll
            for (int np = 0; np < 8; np++) {
                int g = (np << 1) + v_gh;
                uint32_t bv[4];
                ldsm4t(bv, rbase + ((g ^ rsw) << 4));
                mma16816h(oacc[(np << 1) + 0], pa[kt], &bv[0]);
                mma16816h(oacc[(np << 1) + 1], pa[kt], &bv[2]);
            }
        }
    }

#pragma unroll
    for (int m = 1; m < 4; m <<= 1) {
        lsumA += __shfl_xor_sync(0xffffffffu, lsumA, m);
        lsumB += __shfl_xor_sync(0xffffffffu, lsumB, m);
    }

    const int spn = (ks << 1) + wn;
    const long long pb = ((long long)bhk * NSP2 + spn) * 64;
    if (tg == 0) {
        g_pl[pb + (wm << 4) + (l >> 2)]     = lsumA;
        g_pl[pb + (wm << 4) + (l >> 2) + 8] = lsumB;
    }
#pragma unroll
    for (int nt = 0; nt < 16; nt++) {
        long long r0 = pb + (wm << 4) + (l >> 2);
        int d = (nt << 3) + (tg << 1);
        *(float2*)(g_pacc + r0 * 128 + d)       = make_float2(oacc[nt][0], oacc[nt][1]);
        *(float2*)(g_pacc + (r0 + 8) * 128 + d) = make_float2(oacc[nt][2], oacc[nt][3]);
    }
}

// ---------------- combine partials -> zf (fp16) ----------------
__global__ __launch_bounds__(256) void attn_combine(__half* __restrict__ zf)
{
    int idx = blockIdx.x * blockDim.x + threadIdx.x;
    if (idx >= 128 * 64 * 32) return;
    int dq   = idx & 31;
    int row  = (idx >> 5) & 63;
    int bhk  = idx >> 11;
    int d0   = dq << 2;
    float4 a = make_float4(0.f, 0.f, 0.f, 0.f);
    float lv = 0.f;
#pragma unroll
    for (int spn = 0; spn < NSP2; spn++) {
        long long base = ((long long)bhk * NSP2 + spn) * 64 + row;
        float4 t = *(const float4*)(g_pacc + base * 128 + d0);
        a.x += t.x; a.y += t.y; a.z += t.z; a.w += t.w;
        lv += g_pl[base];
    }
    float inv = __frcp_rn(lv);
    int r = row >> 4, n = row & 15;
    int b = bhk >> 3, hk = bhk & 7;
    long long o = (long long)(b * N_ + n) * D_ + (hk * REP_ + r) * DH_ + d0;
    *(uint2*)(zf + o) = make_uint2(cvth2(a.y * inv, a.x * inv),
                                   cvth2(a.w * inv, a.z * inv));
}

// ---------------- launch (fork/join streams) ----------------
extern "C" void kernel_launch(void* const* d_in, const int* in_sizes, int n_in,
                              void* d_out, int out_size)
{
    const float* x  = (const float*)d_in[0];
    const float* fc = (const float*)d_in[1];
    const float* fs = (const float*)d_in[2];
    const float* ck = (const float*)d_in[4];
    const float* cv = (const float*)d_in[5];
    const float* wq = (const float*)d_in[6];
    const float* wk = (const float*)d_in[7];
    const float* wv = (const float*)d_in[8];
    const float* wo = (const float*)d_in[9];
    const int*   sp = (const int*)d_in[10];
    float* out = (float*)d_out;

    int ctx  = in_sizes[4] / (B_ * HK_ * DH_);
    int T    = in_sizes[3] / N_;
    int Tpad = ((T + 63) / 64) * 64;
    if (Tpad > TPC) Tpad = TPC;
    int start_h = T - N_;

    float* pbuf; cudaGetSymbolAddress((void**)&pbuf, g_pbuf);
    __half *xf, *zf;
    cudaGetSymbolAddress((void**)&xf, g_xf);
    cudaGetSymbolAddress((void**)&zf, g_zf);

    static cudaStream_t s2 = []{ cudaStream_t s;
        cudaStreamCreateWithFlags(&s, cudaStreamNonBlocking); return s; }();
    static cudaEvent_t evF = []{ cudaEvent_t e;
        cudaEventCreateWithFlags(&e, cudaEventDisableTiming); return e; }();
    static cudaEvent_t evJ = []{ cudaEvent_t e;
        cudaEventCreateWithFlags(&e, cudaEventDisableTiming); return e; }();

    dim3 blk(256);

    cudaEventRecord(evF, 0);
    cudaStreamWaitEvent(s2, evF, 0);

    // side stream: wo weights + cache-portion K/V conversion
    conv_w<<<dim3(64, 32), blk, 0, s2>>>(wq, wk, wv, wo, 6144);
    conv_kv<<<dim3((128 * start_h * 16 + 255) / 256, 2), blk, 0, s2>>>(
        ck, cv, sp, ctx, Tpad, 0, start_h);
    cudaEventRecord(evJ, s2);

    // main stream
    conv_w<<<dim3(64, 48), blk>>>(wq, wk, wv, wo, 0);
    conv_half<<<(256 * 1024 + 255) / 256, blk>>>(x, xf, 256 * 1024);

    cudaFuncSetAttribute(hgemm, cudaFuncAttributeMaxDynamicSharedMemorySize, HSM_TOT);
    hgemm<<<dim3(96, 2), blk, HSM_TOT>>>(xf, 0, pbuf, PCOLS);

    rope_qk<<<(B_ * N_ * (H_ + HK_) * 64 + 255) / 256, blk>>>(pbuf, fc, fs);
    copy_v<<<(B_ * HK_ * N_ * DH_ + 255) / 256, blk>>>(pbuf);

    conv_kv<<<dim3((128 * (Tpad - start_h) * 16 + 255) / 256, 2), blk>>>(
        ck, cv, sp, ctx, Tpad, start_h, Tpad - start_h);

    cudaStreamWaitEvent(0, evJ, 0);

    cudaFuncSetAttribute(attn, cudaFuncAttributeMaxDynamicSharedMemorySize, ASM_TOT);
    attn<<<dim3(128, 8), blk, ASM_TOT>>>(sp, Tpad);
    attn_combine<<<(128 * 64 * 32 + 255) / 256, blk>>>(zf);

    hgemm<<<dim3(64, 2), blk, HSM_TOT>>>(zf, 6144, out, D_);
}